// round 13
// baseline (speedup 1.0000x reference)
#include <cuda_runtime.h>
#include <cuda_bf16.h>
#include <math.h>
#include <stdint.h>

#define MAXM 200000

// weight plane offsets (elements)
#define WOFF2 0
#define WOFF3 24576          // 3*128*64
#define WOFFF 122880         // WOFF3 + 3*256*128
#define WTOT  319488         // WOFFF + 256*768

// ---------------- static device scratch ----------------
__device__ float g_acc[3 * MAXM * 5];
__device__ float g_t64[(size_t)3 * MAXM * 64];    // layer1 out, pre-BN fp32
__device__ float g_t128[(size_t)3 * MAXM * 128];  // layer2 out, pre-BN fp32
__device__ float g_feat[(size_t)3 * MAXM * 256];  // layer3 out, pre-BN fp32
__device__ float g_y[(size_t)MAXM * 256];         // final pre-BN
__device__ float g_stats[10 * 1536];
__device__ float g_bnp[10 * 1536];
__device__ int   g_idx0[MAXM];
__device__ int   g_idx2[MAXM];
__device__ __nv_bfloat16 g_wh[WTOT];
__device__ __nv_bfloat16 g_wl[WTOT];
// split-bf16 activation planes (post-BN+ReLU), reused between stages
__device__ __nv_bfloat16 g_ah[(size_t)3 * MAXM * 256];
__device__ __nv_bfloat16 g_al[(size_t)3 * MAXM * 256];

// ---------------- zero scratch ----------------
__global__ void zero_kernel() {
    const size_t n1 = (size_t)3 * MAXM * 5;
    const size_t total = n1 + 10 * 1536;
    const size_t stride = (size_t)gridDim.x * blockDim.x;
    for (size_t i = (size_t)blockIdx.x * blockDim.x + threadIdx.x; i < total; i += stride) {
        if (i < n1) g_acc[i] = 0.0f;
        else        g_stats[i - n1] = 0.0f;
    }
}

// ---------------- weight pre-conversion to split bf16 ----------------
__global__ void wconv_kernel(const float* __restrict__ W2, const float* __restrict__ W3,
                             const float* __restrict__ Wf) {
    int i = blockIdx.x * blockDim.x + threadIdx.x;
    if (i >= WTOT) return;
    float v;
    if (i < WOFF3) v = W2[i];
    else if (i < WOFFF) v = W3[i - WOFF3];
    else v = Wf[i - WOFFF];
    __nv_bfloat16 h = __float2bfloat16_rn(v);
    g_wh[i] = h;
    g_wl[i] = __float2bfloat16_rn(v - __bfloat162float(h));
}

// ---------------- scatter ----------------
__global__ void scatter_kernel(const float* __restrict__ pts,
                               const int* __restrict__ inv0,
                               const int* __restrict__ inv1,
                               const int* __restrict__ inv2, int N) {
    int i = blockIdx.x * blockDim.x + threadIdx.x;
    if (i >= N) return;
    float4 p = reinterpret_cast<const float4*>(pts)[i];
    int m0 = inv0[i], m1 = inv1[i], m2 = inv2[i];
    float* a0 = g_acc + (size_t)m0 * 5;
    float* a1 = g_acc + (size_t)MAXM * 5 + (size_t)m1 * 5;
    float* a2 = g_acc + (size_t)2 * MAXM * 5 + (size_t)m2 * 5;
    atomicAdd(a0 + 0, p.x); atomicAdd(a0 + 1, p.y); atomicAdd(a0 + 2, p.z); atomicAdd(a0 + 3, p.w); atomicAdd(a0 + 4, 1.0f);
    atomicAdd(a1 + 0, p.x); atomicAdd(a1 + 1, p.y); atomicAdd(a1 + 2, p.z); atomicAdd(a1 + 3, p.w); atomicAdd(a1 + 4, 1.0f);
    atomicAdd(a2 + 0, p.x); atomicAdd(a2 + 1, p.y); atomicAdd(a2 + 2, p.z); atomicAdd(a2 + 3, p.w); atomicAdd(a2 + 4, 1.0f);
}

// ---------------- fused mean + layer1 (K=4 -> 64) + column stats ----------------
__global__ void l1_kernel(const float* __restrict__ W1, int3 Ms) {
    int s = blockIdx.y;
    int M = (s == 0) ? Ms.x : (s == 1) ? Ms.y : Ms.z;
    __shared__ float Wsm[256];
    __shared__ float s_sum[64], s_sq[64];
    int tid = threadIdx.x;
    Wsm[tid] = W1[s * 256 + tid];
    if (tid < 64) { s_sum[tid] = 0.0f; s_sq[tid] = 0.0f; }
    __syncthreads();
    int lane = tid & 31, w = tid >> 5;
    int c0 = lane * 2;
    float w00 = Wsm[c0 * 4 + 0], w01 = Wsm[c0 * 4 + 1], w02 = Wsm[c0 * 4 + 2], w03 = Wsm[c0 * 4 + 3];
    float w10 = Wsm[c0 * 4 + 4], w11 = Wsm[c0 * 4 + 5], w12 = Wsm[c0 * 4 + 6], w13 = Wsm[c0 * 4 + 7];
    const float* acc = g_acc + (size_t)s * MAXM * 5;
    float* out = g_t64 + (size_t)s * MAXM * 64;
    float sum0 = 0, sq0 = 0, sum1 = 0, sq1 = 0;
    int base = blockIdx.x * 512;
    if (base >= M) return;
    int lim = min(base + 512, M);
    for (int r = base + w; r < lim; r += 8) {
        const float* a = acc + (size_t)r * 5;
        float cnt = fmaxf(__ldg(a + 4), 1.0f);
        float x0 = __ldg(a + 0) / cnt, x1 = __ldg(a + 1) / cnt;
        float x2 = __ldg(a + 2) / cnt, x3 = __ldg(a + 3) / cnt;
        float o0 = x0 * w00 + x1 * w01 + x2 * w02 + x3 * w03;
        float o1 = x0 * w10 + x1 * w11 + x2 * w12 + x3 * w13;
        *reinterpret_cast<float2*>(out + (size_t)r * 64 + c0) = make_float2(o0, o1);
        sum0 += o0; sq0 += o0 * o0; sum1 += o1; sq1 += o1 * o1;
    }
    atomicAdd(&s_sum[c0], sum0);     atomicAdd(&s_sq[c0], sq0);
    atomicAdd(&s_sum[c0 + 1], sum1); atomicAdd(&s_sq[c0 + 1], sq1);
    __syncthreads();
    if (tid < 64) {
        atomicAdd(&g_stats[s * 1536 + tid], s_sum[tid]);
        atomicAdd(&g_stats[s * 1536 + 64 + tid], s_sq[tid]);
    }
}

// ---------------- finalize: raw sum/sumsq -> (scale, shift) ----------------
__global__ void finalize_kernel(const float* __restrict__ st, float* __restrict__ bnp,
                                const float* __restrict__ G, const float* __restrict__ Bb,
                                int C, int3 Ms) {
    int s = blockIdx.y;
    int c = blockIdx.x * blockDim.x + threadIdx.x;
    if (c >= C) return;
    float M = (float)((s == 0) ? Ms.x : (s == 1) ? Ms.y : Ms.z);
    const float* stb = st + (size_t)s * 1536;
    float m = stb[c] / M;
    float v = stb[C + c] / M - m * m;
    float rs = rsqrtf(fmaxf(v, 0.0f) + 1e-5f);
    float sc = rs * G[s * C + c];
    float sh = Bb[s * C + c] - m * sc;
    bnp[(size_t)s * 1536 + c] = sc;
    bnp[(size_t)s * 1536 + C + c] = sh;
}

// ---------------- xform: pre-BN fp32 -> post-BN+ReLU split bf16 planes ----------------
__global__ void xform_kernel(const float* __restrict__ X, int K, int3 Ms,
                             const float* __restrict__ bnp) {
    int s = blockIdx.y;
    int M = (s == 0) ? Ms.x : (s == 1) ? Ms.y : Ms.z;
    const float* Xs = X + (size_t)s * MAXM * K;
    const float* sc = bnp + (size_t)s * 1536;
    const float* sh = sc + K;
    __nv_bfloat16* ahs = g_ah + (size_t)s * MAXM * K;
    __nv_bfloat16* als = g_al + (size_t)s * MAXM * K;
    int kc = K >> 3;
    size_t total = (size_t)M * kc;
    size_t stride = (size_t)gridDim.x * blockDim.x;
    for (size_t idx = (size_t)blockIdx.x * blockDim.x + threadIdx.x; idx < total; idx += stride) {
        size_t m = idx / kc;
        int c8 = (int)(idx - m * kc) * 8;
        const float* p = Xs + m * K + c8;
        float4 v0 = *reinterpret_cast<const float4*>(p);
        float4 v1 = *reinterpret_cast<const float4*>(p + 4);
        float vv[8] = {v0.x, v0.y, v0.z, v0.w, v1.x, v1.y, v1.z, v1.w};
        __nv_bfloat16 hh[8], ll[8];
        #pragma unroll
        for (int c = 0; c < 8; c++) {
            float t = fmaxf(vv[c] * __ldg(sc + c8 + c) + __ldg(sh + c8 + c), 0.0f);
            __nv_bfloat16 h = __float2bfloat16_rn(t);
            hh[c] = h;
            ll[c] = __float2bfloat16_rn(t - __bfloat162float(h));
        }
        *reinterpret_cast<uint4*>(ahs + m * K + c8) = *reinterpret_cast<uint4*>(hh);
        *reinterpret_cast<uint4*>(als + m * K + c8) = *reinterpret_cast<uint4*>(ll);
    }
}

// ---------------- mma helpers ----------------
__device__ __forceinline__ uint32_t smem_u32(const void* p) {
    uint32_t a;
    asm("{ .reg .u64 t; cvta.to.shared.u64 t, %1; cvt.u32.u64 %0, t; }" : "=r"(a) : "l"(p));
    return a;
}
__device__ __forceinline__ void mma_bf16(float* d, const uint32_t* a, const uint32_t* b) {
    asm volatile(
        "mma.sync.aligned.m16n8k16.row.col.f32.bf16.bf16.f32 "
        "{%0,%1,%2,%3}, {%4,%5,%6,%7}, {%8,%9}, {%0,%1,%2,%3};"
        : "+f"(d[0]), "+f"(d[1]), "+f"(d[2]), "+f"(d[3])
        : "r"(a[0]), "r"(a[1]), "r"(a[2]), "r"(a[3]), "r"(b[0]), "r"(b[1]));
}
__device__ __forceinline__ void ldsm_x4(uint32_t* r, uint32_t addr) {
    asm volatile("ldmatrix.sync.aligned.m8n8.x4.shared.b16 {%0,%1,%2,%3}, [%4];"
                 : "=r"(r[0]), "=r"(r[1]), "=r"(r[2]), "=r"(r[3]) : "r"(addr));
}
__device__ __forceinline__ void ldsm_x2(uint32_t* r, uint32_t addr) {
    asm volatile("ldmatrix.sync.aligned.m8n8.x2.shared.b16 {%0,%1}, [%2];"
                 : "=r"(r[0]), "=r"(r[1]) : "r"(addr));
}
__device__ __forceinline__ void cp_async16(uint32_t dst, const void* src) {
    asm volatile("cp.async.cg.shared.global [%0], [%1], 16;" :: "r"(dst), "l"(src) : "memory");
}
__device__ __forceinline__ void cp_async16z(uint32_t dst, const void* src, uint32_t srcsz) {
    asm volatile("cp.async.cg.shared.global [%0], [%1], 16, %2;"
                 :: "r"(dst), "l"(src), "r"(srcsz) : "memory");
}
__device__ __forceinline__ void cp_commit() {
    asm volatile("cp.async.commit_group;" ::: "memory");
}
__device__ __forceinline__ void cp_wait_all() {
    asm volatile("cp.async.wait_group 0;" ::: "memory");
}

// ---------------- pure-async bf16x2-split tensor GEMM ----------------
// CTA 128x128, 8 warps (warp tile 64x32), K-chunk 32, double buffered.
// A and B both arrive pre-split bf16 via cp.async; no register transforms in the loop.
// Smem rows 64B data + 16B pad (80B stride, conflict-free ldmatrix).
// MODE 1: A rows contiguous in plane (s*MAXM rows). MODE 2: gathered rows (768-K concat).
template<int MODE>
__global__ void __launch_bounds__(256, 2)
mma_gemm(int K, int woff, size_t Wstr,
         float* __restrict__ Cbase, size_t Cstr,
         int3 Ms, int N,
         float* __restrict__ stbase) {
    constexpr int RS = 20;               // smem row stride in u32 (80B)
    int s = blockIdx.z;
    int M = (MODE == 2) ? Ms.y : ((s == 0) ? Ms.x : (s == 1) ? Ms.y : Ms.z);
    int bm = blockIdx.y * 128;
    if (bm >= M) return;
    int bn = blockIdx.x * 128;

    const __nv_bfloat16* Ah = g_ah + (size_t)s * MAXM * K;   // MODE 1 base (s=0 for MODE 2)
    const __nv_bfloat16* Al = g_al + (size_t)s * MAXM * K;
    const __nv_bfloat16* Wh = g_wh + woff + (size_t)s * Wstr;
    const __nv_bfloat16* Wl = g_wl + woff + (size_t)s * Wstr;
    float* Cp = Cbase + (size_t)s * Cstr;
    float* st = stbase + (size_t)s * 1536;

    __shared__ uint32_t sAh[2][128 * RS], sAl[2][128 * RS];
    __shared__ uint32_t sBh[2][128 * RS], sBl[2][128 * RS];
    __shared__ float s_sum[128], s_sq[128];

    int tid = threadIdx.x;
    int lane = tid & 31, warp = tid >> 5;
    int warpM = warp & 1, warpN = warp >> 1;

    for (int c = tid; c < 128; c += 256) { s_sum[c] = 0.0f; s_sq[c] = 0.0f; }

    uint32_t baseAh = smem_u32(sAh[0]), baseAl = smem_u32(sAl[0]);
    uint32_t baseBh = smem_u32(sBh[0]), baseBl = smem_u32(sBl[0]);

    float acc[4][4][4];
    #pragma unroll
    for (int f = 0; f < 4; f++)
        #pragma unroll
        for (int g = 0; g < 4; g++)
            #pragma unroll
            for (int r = 0; r < 4; r++) acc[f][g][r] = 0.0f;

    int a_row = lane & 15;
    int a_koff = (lane & 16) ? 16 : 0;
    int b_row = lane & 7;
    int b_koff = (lane & 8) ? 16 : 0;

    auto issueAB = [&](int t, int buf) {
        int tk = t * 32;
        uint32_t ah0 = baseAh + (uint32_t)buf * (128 * RS * 4);
        uint32_t al0 = baseAl + (uint32_t)buf * (128 * RS * 4);
        uint32_t bh0 = baseBh + (uint32_t)buf * (128 * RS * 4);
        uint32_t bl0 = baseBl + (uint32_t)buf * (128 * RS * 4);
        #pragma unroll
        for (int i = 0; i < 2; i++) {
            int v = tid + i * 256;
            int r = v >> 2, q = v & 3;
            int gk = tk + q * 8;
            uint32_t dst = (uint32_t)(r * 80 + q * 16);
            // A row r
            if (MODE == 1) {
                int gm = bm + r;
                cp_async16(ah0 + dst, Ah + (size_t)gm * K + gk);
                cp_async16(al0 + dst, Al + (size_t)gm * K + gk);
            } else {
                int gm = bm + r;
                int seg = gk >> 8, off = gk & 255;
                int j = -1;
                if (gm < M) {
                    if (seg == 0) j = g_idx0[gm];
                    else if (seg == 1) j = gm;
                    else j = g_idx2[gm];
                }
                uint32_t ok = (j >= 0) ? 16u : 0u;
                size_t srow = (size_t)seg * MAXM + (j >= 0 ? j : 0);
                cp_async16z(ah0 + dst, g_ah + srow * 256 + off, ok);
                cp_async16z(al0 + dst, g_al + srow * 256 + off, ok);
            }
            // B row r
            int gn = bn + r;
            cp_async16(bh0 + dst, Wh + (size_t)gn * K + gk);
            cp_async16(bl0 + dst, Wl + (size_t)gn * K + gk);
        }
        cp_commit();
    };

    int nch = K / 32;
    issueAB(0, 0);

    for (int t = 0; t < nch; t++) {
        cp_wait_all();
        __syncthreads();
        if (t + 1 < nch) issueAB(t + 1, (t + 1) & 1);
        int buf = t & 1;
        uint32_t aoff = (uint32_t)buf * (128 * RS * 4);

        #pragma unroll
        for (int kk = 0; kk < 32; kk += 16) {
            uint32_t bh[4][2], bl[4][2];
            #pragma unroll
            for (int g = 0; g < 4; g++) {
                int n0 = warpN * 32 + g * 8;
                uint32_t off = aoff + (uint32_t)((n0 + b_row) * 80 + kk * 2 + b_koff);
                ldsm_x2(bh[g], baseBh + off);
                ldsm_x2(bl[g], baseBl + off);
            }
            #pragma unroll
            for (int f = 0; f < 4; f++) {
                int m0 = warpM * 64 + f * 16;
                uint32_t off = aoff + (uint32_t)((m0 + a_row) * 80 + kk * 2 + a_koff);
                uint32_t ah[4], al[4];
                ldsm_x4(ah, baseAh + off);
                ldsm_x4(al, baseAl + off);
                #pragma unroll
                for (int g = 0; g < 4; g++) {
                    mma_bf16(acc[f][g], ah, bh[g]);
                    mma_bf16(acc[f][g], ah, bl[g]);
                    mma_bf16(acc[f][g], al, bh[g]);
                }
            }
        }
    }

    // ---- epilogue: store C + fused column stats ----
    float csum[4][2], csq[4][2];
    #pragma unroll
    for (int g = 0; g < 4; g++) { csum[g][0] = csum[g][1] = 0.f; csq[g][0] = csq[g][1] = 0.f; }

    int qr = lane >> 2, qc = lane & 3;
    #pragma unroll
    for (int f = 0; f < 4; f++) {
        int r0 = bm + warpM * 64 + f * 16 + qr;
        int r1 = r0 + 8;
        #pragma unroll
        for (int g = 0; g < 4; g++) {
            int c0 = bn + warpN * 32 + g * 8 + 2 * qc;
            if (r0 < M) {
                *reinterpret_cast<float2*>(Cp + (size_t)r0 * N + c0) =
                    make_float2(acc[f][g][0], acc[f][g][1]);
                csum[g][0] += acc[f][g][0]; csq[g][0] += acc[f][g][0] * acc[f][g][0];
                csum[g][1] += acc[f][g][1]; csq[g][1] += acc[f][g][1] * acc[f][g][1];
            }
            if (r1 < M) {
                *reinterpret_cast<float2*>(Cp + (size_t)r1 * N + c0) =
                    make_float2(acc[f][g][2], acc[f][g][3]);
                csum[g][0] += acc[f][g][2]; csq[g][0] += acc[f][g][2] * acc[f][g][2];
                csum[g][1] += acc[f][g][3]; csq[g][1] += acc[f][g][3] * acc[f][g][3];
            }
        }
    }
    __syncthreads();   // reuse of s_sum after main loop
    #pragma unroll
    for (int g = 0; g < 4; g++) {
        int cl = warpN * 32 + g * 8 + 2 * qc;
        atomicAdd(&s_sum[cl], csum[g][0]);     atomicAdd(&s_sq[cl], csq[g][0]);
        atomicAdd(&s_sum[cl + 1], csum[g][1]); atomicAdd(&s_sq[cl + 1], csq[g][1]);
    }
    __syncthreads();
    for (int c = tid; c < 128; c += 256) {
        atomicAdd(&st[bn + c],     s_sum[c]);
        atomicAdd(&st[N + bn + c], s_sq[c]);
    }
}

// ---------------- BN + ReLU (final output only) ----------------
__global__ void bnrelu_kernel(const float* __restrict__ Y, float* __restrict__ Z,
                              int M, int C, const float* __restrict__ st,
                              const float* __restrict__ G, const float* __restrict__ B) {
    size_t total = (size_t)M * C;
    size_t stride = (size_t)gridDim.x * blockDim.x;
    float invM = 1.0f / (float)M;
    for (size_t i = (size_t)blockIdx.x * blockDim.x + threadIdx.x; i < total; i += stride) {
        int c = (int)(i % C);
        float m = st[c] * invM;
        float v = st[C + c] * invM - m * m;
        float sc = rsqrtf(fmaxf(v, 0.0f) + 1e-5f);
        float z = (Y[i] - m) * sc * G[c] + B[c];
        Z[i] = fmaxf(z, 0.0f);
    }
}

// ---------------- alignment (matches jitted reference bit-exactly) ----------------
__device__ __forceinline__ int lower_bound_i32(const int* __restrict__ a, int n, int key) {
    int lo = 0, hi = n;
    while (lo < hi) {
        int mid = (lo + hi) >> 1;
        if (a[mid] < key) lo = mid + 1; else hi = mid;
    }
    return lo;
}

__global__ void align_kernel(const int* __restrict__ uc1, int M1,
                             const int* __restrict__ keys0, int M0,
                             const int* __restrict__ keys2, int M2) {
    int i = blockIdx.x * blockDim.x + threadIdx.x;
    if (i >= M1) return;
    int b  = uc1[4 * i + 0];
    int cx = uc1[4 * i + 1];
    int cy = uc1[4 * i + 2];
    int cz = uc1[4 * i + 3];
    float rx = __fadd_rn(__fmul_rn(__fadd_rn((float)cx, 0.5f), 0.2f), -50.0f);
    float ry = __fadd_rn(__fmul_rn(__fadd_rn((float)cy, 0.5f), 0.2f), -50.0f);
    float rz = __fadd_rn(__fmul_rn(__fadd_rn((float)cz, 0.5f), 0.2f), -3.0f);
    float dx = __fsub_rn(rx, -50.0f);
    float dy = __fsub_rn(ry, -50.0f);
    float dz = __fsub_rn(rz, -3.0f);
    {
        int ix = (int)floorf(__fmul_rn(dx, 10.0f)); ix = min(max(ix, 0), 999);
        int iy = (int)floorf(__fmul_rn(dy, 10.0f)); iy = min(max(iy, 0), 999);
        int iz = (int)floorf(__fmul_rn(dz, 10.0f)); iz = min(max(iz, 0), 59);
        int k = b * 1000000000 + ix * 1000000 + iy * 1000 + iz;
        int lo = lower_bound_i32(keys0, M0, k);
        int idx = min(lo, M0 - 1); if (idx < 0) idx = 0;
        g_idx0[i] = (keys0[idx] == k) ? idx : -1;
    }
    {
        int ix = (int)floorf(__fmul_rn(dx, 2.5f)); ix = min(max(ix, 0), 249);
        int iy = (int)floorf(__fmul_rn(dy, 2.5f)); iy = min(max(iy, 0), 249);
        int iz = (int)floorf(__fmul_rn(dz, 2.5f)); iz = min(max(iz, 0), 14);
        int k = b * 1000000000 + ix * 1000000 + iy * 1000 + iz;
        int lo = lower_bound_i32(keys2, M2, k);
        int idx = min(lo, M2 - 1); if (idx < 0) idx = 0;
        g_idx2[i] = (keys2[idx] == k) ? idx : -1;
    }
}

// ---------------- host orchestration ----------------
extern "C" void kernel_launch(void* const* d_in, const int* in_sizes, int n_in,
                              void* d_out, int out_size) {
    (void)n_in; (void)out_size;
    const float* points = (const float*)d_in[0];
    const float* W1 = (const float*)d_in[1];
    const float* G1 = (const float*)d_in[2];
    const float* B1 = (const float*)d_in[3];
    const float* W2 = (const float*)d_in[4];
    const float* G2 = (const float*)d_in[5];
    const float* B2 = (const float*)d_in[6];
    const float* W3 = (const float*)d_in[7];
    const float* G3 = (const float*)d_in[8];
    const float* B3 = (const float*)d_in[9];
    const float* Wf = (const float*)d_in[10];
    const float* Gf = (const float*)d_in[11];
    const float* Bf = (const float*)d_in[12];
    const int* inv0 = (const int*)d_in[13];
    const int* inv1 = (const int*)d_in[14];
    const int* inv2 = (const int*)d_in[15];
    const int* keys0 = (const int*)d_in[16];
    const int* keys2 = (const int*)d_in[17];
    const int* uc1   = (const int*)d_in[18];

    int N  = in_sizes[0] / 4;
    int M0 = in_sizes[16];
    int M2 = in_sizes[17];
    int M1 = in_sizes[18] / 4;
    int maxM = M0 > M1 ? M0 : M1; if (M2 > maxM) maxM = M2;
    int3 Ms3 = make_int3(M0, M1, M2);

    float *t64, *t128, *feat, *y, *stats, *bnp;
    cudaGetSymbolAddress((void**)&t64,  g_t64);
    cudaGetSymbolAddress((void**)&t128, g_t128);
    cudaGetSymbolAddress((void**)&feat, g_feat);
    cudaGetSymbolAddress((void**)&y,    g_y);
    cudaGetSymbolAddress((void**)&stats, g_stats);
    cudaGetSymbolAddress((void**)&bnp,   g_bnp);

    zero_kernel<<<2048, 256>>>();
    wconv_kernel<<<(WTOT + 255) / 256, 256>>>(W2, W3, Wf);
    scatter_kernel<<<(N + 255) / 256, 256>>>(points, inv0, inv1, inv2, N);
    align_kernel<<<(M1 + 255) / 256, 256>>>(uc1, M1, keys0, M0, keys2, M2);

    // Layer 1 fused (mean + K=4 GEMM + stats)
    l1_kernel<<<dim3((maxM + 511) / 512, 3), 256>>>(W1, Ms3);
    finalize_kernel<<<dim3(1, 3), 64>>>(stats, bnp, G1, B1, 64, Ms3);
    xform_kernel<<<dim3(512, 3), 256>>>(t64, 64, Ms3, bnp);

    int gy = (maxM + 127) / 128;

    // Layer 2: [M,64] -> [M,128]
    mma_gemm<1><<<dim3(1, gy, 3), 256>>>(64, WOFF2, 128 * 64,
                                         t128, (size_t)MAXM * 128, Ms3, 128,
                                         stats + 4608);
    finalize_kernel<<<dim3(1, 3), 128>>>(stats + 4608, bnp + 4608, G2, B2, 128, Ms3);
    xform_kernel<<<dim3(512, 3), 256>>>(t128, 128, Ms3, bnp + 4608);

    // Layer 3: [M,128] -> [M,256]
    mma_gemm<1><<<dim3(2, gy, 3), 256>>>(128, WOFF3, 256 * 128,
                                         feat, (size_t)MAXM * 256, Ms3, 256,
                                         stats + 9216);
    finalize_kernel<<<dim3(1, 3), 256>>>(stats + 9216, bnp + 9216, G3, B3, 256, Ms3);
    xform_kernel<<<dim3(512, 3), 256>>>(feat, 256, Ms3, bnp + 9216);

    // Final: gather [M1,768] -> [M1,256]
    mma_gemm<2><<<dim3(2, (M1 + 127) / 128, 1), 256>>>(768, WOFFF, 0,
                                                       y, 0, Ms3, 256,
                                                       stats + 13824);

    bnrelu_kernel<<<4096, 256>>>(y, (float*)d_out, M1, 256, stats + 13824, Gf, Bf);
}

// round 14
// speedup vs baseline: 1.0031x; 1.0031x over previous
#include <cuda_runtime.h>
#include <cuda_bf16.h>
#include <math.h>
#include <stdint.h>

#define MAXM 200000

// weight plane offsets (elements)
#define WOFF2 0
#define WOFF3 24576          // 3*128*64
#define WOFFF 122880         // WOFF3 + 3*256*128
#define WTOT  319488         // WOFFF + 256*768

// ---------------- static device scratch ----------------
__device__ float g_acc[3 * MAXM * 5];
__device__ float g_t64[(size_t)3 * MAXM * 64];    // layer1 out, pre-BN fp32
__device__ float g_t128[(size_t)3 * MAXM * 128];  // layer2 out, pre-BN fp32
__device__ float g_feat[(size_t)3 * MAXM * 256];  // layer3 out, pre-BN fp32
__device__ float g_y[(size_t)MAXM * 256];         // final pre-BN
__device__ float g_stats[10 * 1536];
__device__ float g_bnp[10 * 1536];
__device__ int   g_idx0[MAXM];
__device__ int   g_idx2[MAXM];
__device__ __nv_bfloat16 g_wh[WTOT];
__device__ __nv_bfloat16 g_wl[WTOT];
// split-bf16 activation planes (post-BN+ReLU), reused between stages
__device__ __nv_bfloat16 g_ah[(size_t)3 * MAXM * 256];
__device__ __nv_bfloat16 g_al[(size_t)3 * MAXM * 256];

// ---------------- zero scratch ----------------
__global__ void zero_kernel() {
    const size_t n1 = (size_t)3 * MAXM * 5;
    const size_t total = n1 + 10 * 1536;
    const size_t stride = (size_t)gridDim.x * blockDim.x;
    for (size_t i = (size_t)blockIdx.x * blockDim.x + threadIdx.x; i < total; i += stride) {
        if (i < n1) g_acc[i] = 0.0f;
        else        g_stats[i - n1] = 0.0f;
    }
}

// ---------------- weight pre-conversion to split bf16 ----------------
__global__ void wconv_kernel(const float* __restrict__ W2, const float* __restrict__ W3,
                             const float* __restrict__ Wf) {
    int i = blockIdx.x * blockDim.x + threadIdx.x;
    if (i >= WTOT) return;
    float v;
    if (i < WOFF3) v = W2[i];
    else if (i < WOFFF) v = W3[i - WOFF3];
    else v = Wf[i - WOFFF];
    __nv_bfloat16 h = __float2bfloat16_rn(v);
    g_wh[i] = h;
    g_wl[i] = __float2bfloat16_rn(v - __bfloat162float(h));
}

// ---------------- scatter ----------------
__global__ void scatter_kernel(const float* __restrict__ pts,
                               const int* __restrict__ inv0,
                               const int* __restrict__ inv1,
                               const int* __restrict__ inv2, int N) {
    int i = blockIdx.x * blockDim.x + threadIdx.x;
    if (i >= N) return;
    float4 p = reinterpret_cast<const float4*>(pts)[i];
    int m0 = inv0[i], m1 = inv1[i], m2 = inv2[i];
    float* a0 = g_acc + (size_t)m0 * 5;
    float* a1 = g_acc + (size_t)MAXM * 5 + (size_t)m1 * 5;
    float* a2 = g_acc + (size_t)2 * MAXM * 5 + (size_t)m2 * 5;
    atomicAdd(a0 + 0, p.x); atomicAdd(a0 + 1, p.y); atomicAdd(a0 + 2, p.z); atomicAdd(a0 + 3, p.w); atomicAdd(a0 + 4, 1.0f);
    atomicAdd(a1 + 0, p.x); atomicAdd(a1 + 1, p.y); atomicAdd(a1 + 2, p.z); atomicAdd(a1 + 3, p.w); atomicAdd(a1 + 4, 1.0f);
    atomicAdd(a2 + 0, p.x); atomicAdd(a2 + 1, p.y); atomicAdd(a2 + 2, p.z); atomicAdd(a2 + 3, p.w); atomicAdd(a2 + 4, 1.0f);
}

// ---------------- fused mean + layer1 (K=4 -> 64) + column stats ----------------
__global__ void l1_kernel(const float* __restrict__ W1, int3 Ms) {
    int s = blockIdx.y;
    int M = (s == 0) ? Ms.x : (s == 1) ? Ms.y : Ms.z;
    __shared__ float Wsm[256];
    __shared__ float s_sum[64], s_sq[64];
    int tid = threadIdx.x;
    Wsm[tid] = W1[s * 256 + tid];
    if (tid < 64) { s_sum[tid] = 0.0f; s_sq[tid] = 0.0f; }
    __syncthreads();
    int lane = tid & 31, w = tid >> 5;
    int c0 = lane * 2;
    float w00 = Wsm[c0 * 4 + 0], w01 = Wsm[c0 * 4 + 1], w02 = Wsm[c0 * 4 + 2], w03 = Wsm[c0 * 4 + 3];
    float w10 = Wsm[c0 * 4 + 4], w11 = Wsm[c0 * 4 + 5], w12 = Wsm[c0 * 4 + 6], w13 = Wsm[c0 * 4 + 7];
    const float* acc = g_acc + (size_t)s * MAXM * 5;
    float* out = g_t64 + (size_t)s * MAXM * 64;
    float sum0 = 0, sq0 = 0, sum1 = 0, sq1 = 0;
    int base = blockIdx.x * 512;
    if (base >= M) return;
    int lim = min(base + 512, M);
    for (int r = base + w; r < lim; r += 8) {
        const float* a = acc + (size_t)r * 5;
        float cnt = fmaxf(__ldg(a + 4), 1.0f);
        float x0 = __ldg(a + 0) / cnt, x1 = __ldg(a + 1) / cnt;
        float x2 = __ldg(a + 2) / cnt, x3 = __ldg(a + 3) / cnt;
        float o0 = x0 * w00 + x1 * w01 + x2 * w02 + x3 * w03;
        float o1 = x0 * w10 + x1 * w11 + x2 * w12 + x3 * w13;
        *reinterpret_cast<float2*>(out + (size_t)r * 64 + c0) = make_float2(o0, o1);
        sum0 += o0; sq0 += o0 * o0; sum1 += o1; sq1 += o1 * o1;
    }
    atomicAdd(&s_sum[c0], sum0);     atomicAdd(&s_sq[c0], sq0);
    atomicAdd(&s_sum[c0 + 1], sum1); atomicAdd(&s_sq[c0 + 1], sq1);
    __syncthreads();
    if (tid < 64) {
        atomicAdd(&g_stats[s * 1536 + tid], s_sum[tid]);
        atomicAdd(&g_stats[s * 1536 + 64 + tid], s_sq[tid]);
    }
}

// ---------------- finalize: raw sum/sumsq -> (scale, shift) ----------------
__global__ void finalize_kernel(const float* __restrict__ st, float* __restrict__ bnp,
                                const float* __restrict__ G, const float* __restrict__ Bb,
                                int C, int3 Ms) {
    int s = blockIdx.y;
    int c = blockIdx.x * blockDim.x + threadIdx.x;
    if (c >= C) return;
    float M = (float)((s == 0) ? Ms.x : (s == 1) ? Ms.y : Ms.z);
    const float* stb = st + (size_t)s * 1536;
    float m = stb[c] / M;
    float v = stb[C + c] / M - m * m;
    float rs = rsqrtf(fmaxf(v, 0.0f) + 1e-5f);
    float sc = rs * G[s * C + c];
    float sh = Bb[s * C + c] - m * sc;
    bnp[(size_t)s * 1536 + c] = sc;
    bnp[(size_t)s * 1536 + C + c] = sh;
}

// ---------------- xform: pre-BN fp32 -> post-BN+ReLU split bf16 planes ----------------
__global__ void xform_kernel(const float* __restrict__ X, int K, int3 Ms,
                             const float* __restrict__ bnp) {
    int s = blockIdx.y;
    int M = (s == 0) ? Ms.x : (s == 1) ? Ms.y : Ms.z;
    const float* Xs = X + (size_t)s * MAXM * K;
    const float* sc = bnp + (size_t)s * 1536;
    const float* sh = sc + K;
    __nv_bfloat16* ahs = g_ah + (size_t)s * MAXM * K;
    __nv_bfloat16* als = g_al + (size_t)s * MAXM * K;
    int kc = K >> 3;
    size_t total = (size_t)M * kc;
    size_t stride = (size_t)gridDim.x * blockDim.x;
    for (size_t idx = (size_t)blockIdx.x * blockDim.x + threadIdx.x; idx < total; idx += stride) {
        size_t m = idx / kc;
        int c8 = (int)(idx - m * kc) * 8;
        const float* p = Xs + m * K + c8;
        float4 v0 = *reinterpret_cast<const float4*>(p);
        float4 v1 = *reinterpret_cast<const float4*>(p + 4);
        float vv[8] = {v0.x, v0.y, v0.z, v0.w, v1.x, v1.y, v1.z, v1.w};
        __nv_bfloat16 hh[8], ll[8];
        #pragma unroll
        for (int c = 0; c < 8; c++) {
            float t = fmaxf(vv[c] * __ldg(sc + c8 + c) + __ldg(sh + c8 + c), 0.0f);
            __nv_bfloat16 h = __float2bfloat16_rn(t);
            hh[c] = h;
            ll[c] = __float2bfloat16_rn(t - __bfloat162float(h));
        }
        *reinterpret_cast<uint4*>(ahs + m * K + c8) = *reinterpret_cast<uint4*>(hh);
        *reinterpret_cast<uint4*>(als + m * K + c8) = *reinterpret_cast<uint4*>(ll);
    }
}

// ---------------- mma helpers ----------------
__device__ __forceinline__ uint32_t smem_u32(const void* p) {
    uint32_t a;
    asm("{ .reg .u64 t; cvta.to.shared.u64 t, %1; cvt.u32.u64 %0, t; }" : "=r"(a) : "l"(p));
    return a;
}
__device__ __forceinline__ void mma_bf16(float* d, const uint32_t* a, const uint32_t* b) {
    asm volatile(
        "mma.sync.aligned.m16n8k16.row.col.f32.bf16.bf16.f32 "
        "{%0,%1,%2,%3}, {%4,%5,%6,%7}, {%8,%9}, {%0,%1,%2,%3};"
        : "+f"(d[0]), "+f"(d[1]), "+f"(d[2]), "+f"(d[3])
        : "r"(a[0]), "r"(a[1]), "r"(a[2]), "r"(a[3]), "r"(b[0]), "r"(b[1]));
}
__device__ __forceinline__ void ldsm_x4(uint32_t* r, uint32_t addr) {
    asm volatile("ldmatrix.sync.aligned.m8n8.x4.shared.b16 {%0,%1,%2,%3}, [%4];"
                 : "=r"(r[0]), "=r"(r[1]), "=r"(r[2]), "=r"(r[3]) : "r"(addr));
}
__device__ __forceinline__ void cp_async16(uint32_t dst, const void* src) {
    asm volatile("cp.async.cg.shared.global [%0], [%1], 16;" :: "r"(dst), "l"(src) : "memory");
}
__device__ __forceinline__ void cp_async16z(uint32_t dst, const void* src, uint32_t srcsz) {
    asm volatile("cp.async.cg.shared.global [%0], [%1], 16, %2;"
                 :: "r"(dst), "l"(src), "r"(srcsz) : "memory");
}
__device__ __forceinline__ void cp_commit() {
    asm volatile("cp.async.commit_group;" ::: "memory");
}
__device__ __forceinline__ void cp_wait_all() {
    asm volatile("cp.async.wait_group 0;" ::: "memory");
}

// ---------------- pure-async bf16x2-split tensor GEMM ----------------
// CTA 128x128, 8 warps (warp tile 64x32), K-chunk 32, double buffered.
// A and B both arrive pre-split bf16 via cp.async; no register transforms in the loop.
// Smem rows 64B data + 16B pad (80B stride, conflict-free ldmatrix).
// B fragments loaded with ldsm.x4 (two n-groups per issue) -> 12 LDSM/warp/k16 vs 16.
// MODE 1: A rows contiguous in plane. MODE 2: gathered rows (768-K concat).
template<int MODE>
__global__ void __launch_bounds__(256, 2)
mma_gemm(int K, int woff, size_t Wstr,
         float* __restrict__ Cbase, size_t Cstr,
         int3 Ms, int N,
         float* __restrict__ stbase) {
    constexpr int RS = 20;               // smem row stride in u32 (80B)
    int s = blockIdx.z;
    int M = (MODE == 2) ? Ms.y : ((s == 0) ? Ms.x : (s == 1) ? Ms.y : Ms.z);
    int bm = blockIdx.y * 128;
    if (bm >= M) return;
    int bn = blockIdx.x * 128;

    const __nv_bfloat16* Ah = g_ah + (size_t)s * MAXM * K;
    const __nv_bfloat16* Al = g_al + (size_t)s * MAXM * K;
    const __nv_bfloat16* Wh = g_wh + woff + (size_t)s * Wstr;
    const __nv_bfloat16* Wl = g_wl + woff + (size_t)s * Wstr;
    float* Cp = Cbase + (size_t)s * Cstr;
    float* st = stbase + (size_t)s * 1536;

    __shared__ uint32_t sAh[2][128 * RS], sAl[2][128 * RS];
    __shared__ uint32_t sBh[2][128 * RS], sBl[2][128 * RS];
    __shared__ float s_sum[128], s_sq[128];

    int tid = threadIdx.x;
    int lane = tid & 31, warp = tid >> 5;
    int warpM = warp & 1, warpN = warp >> 1;

    for (int c = tid; c < 128; c += 256) { s_sum[c] = 0.0f; s_sq[c] = 0.0f; }

    uint32_t baseAh = smem_u32(sAh[0]), baseAl = smem_u32(sAl[0]);
    uint32_t baseBh = smem_u32(sBh[0]), baseBl = smem_u32(sBl[0]);

    float acc[4][4][4];
    #pragma unroll
    for (int f = 0; f < 4; f++)
        #pragma unroll
        for (int g = 0; g < 4; g++)
            #pragma unroll
            for (int r = 0; r < 4; r++) acc[f][g][r] = 0.0f;

    int a_row = lane & 15;
    int a_koff = (lane & 16) ? 16 : 0;
    // B x4 addressing: matrices 0,1 = n-group g (k0-7, k8-15); 2,3 = n-group g+1
    int b4_row = (lane & 7) + ((lane & 16) ? 8 : 0);
    int b4_koff = (lane & 8) ? 16 : 0;

    auto issueAB = [&](int t, int buf) {
        int tk = t * 32;
        uint32_t ah0 = baseAh + (uint32_t)buf * (128 * RS * 4);
        uint32_t al0 = baseAl + (uint32_t)buf * (128 * RS * 4);
        uint32_t bh0 = baseBh + (uint32_t)buf * (128 * RS * 4);
        uint32_t bl0 = baseBl + (uint32_t)buf * (128 * RS * 4);
        #pragma unroll
        for (int i = 0; i < 2; i++) {
            int v = tid + i * 256;
            int r = v >> 2, q = v & 3;
            int gk = tk + q * 8;
            uint32_t dst = (uint32_t)(r * 80 + q * 16);
            if (MODE == 1) {
                int gm = bm + r;
                cp_async16(ah0 + dst, Ah + (size_t)gm * K + gk);
                cp_async16(al0 + dst, Al + (size_t)gm * K + gk);
            } else {
                int gm = bm + r;
                int seg = gk >> 8, off = gk & 255;
                int j = -1;
                if (gm < M) {
                    if (seg == 0) j = g_idx0[gm];
                    else if (seg == 1) j = gm;
                    else j = g_idx2[gm];
                }
                uint32_t ok = (j >= 0) ? 16u : 0u;
                size_t srow = (size_t)seg * MAXM + (j >= 0 ? j : 0);
                cp_async16z(ah0 + dst, g_ah + srow * 256 + off, ok);
                cp_async16z(al0 + dst, g_al + srow * 256 + off, ok);
            }
            int gn = bn + r;
            cp_async16(bh0 + dst, Wh + (size_t)gn * K + gk);
            cp_async16(bl0 + dst, Wl + (size_t)gn * K + gk);
        }
        cp_commit();
    };

    int nch = K / 32;
    issueAB(0, 0);

    for (int t = 0; t < nch; t++) {
        cp_wait_all();
        __syncthreads();
        if (t + 1 < nch) issueAB(t + 1, (t + 1) & 1);
        int buf = t & 1;
        uint32_t aoff = (uint32_t)buf * (128 * RS * 4);

        #pragma unroll
        for (int kk = 0; kk < 32; kk += 16) {
            uint32_t bh[4][2], bl[4][2];
            #pragma unroll
            for (int gp = 0; gp < 2; gp++) {
                int n0 = warpN * 32 + gp * 16;
                uint32_t off = aoff + (uint32_t)((n0 + b4_row) * 80 + kk * 2 + b4_koff);
                uint32_t tm[4];
                ldsm_x4(tm, baseBh + off);
                bh[2 * gp][0] = tm[0]; bh[2 * gp][1] = tm[1];
                bh[2 * gp + 1][0] = tm[2]; bh[2 * gp + 1][1] = tm[3];
                ldsm_x4(tm, baseBl + off);
                bl[2 * gp][0] = tm[0]; bl[2 * gp][1] = tm[1];
                bl[2 * gp + 1][0] = tm[2]; bl[2 * gp + 1][1] = tm[3];
            }
            #pragma unroll
            for (int f = 0; f < 4; f++) {
                int m0 = warpM * 64 + f * 16;
                uint32_t off = aoff + (uint32_t)((m0 + a_row) * 80 + kk * 2 + a_koff);
                uint32_t ah[4], al[4];
                ldsm_x4(ah, baseAh + off);
                ldsm_x4(al, baseAl + off);
                #pragma unroll
                for (int g = 0; g < 4; g++) {
                    mma_bf16(acc[f][g], ah, bh[g]);
                    mma_bf16(acc[f][g], ah, bl[g]);
                    mma_bf16(acc[f][g], al, bh[g]);
                }
            }
        }
    }

    // ---- epilogue: store C + fused column stats ----
    float csum[4][2], csq[4][2];
    #pragma unroll
    for (int g = 0; g < 4; g++) { csum[g][0] = csum[g][1] = 0.f; csq[g][0] = csq[g][1] = 0.f; }

    int qr = lane >> 2, qc = lane & 3;
    #pragma unroll
    for (int f = 0; f < 4; f++) {
        int r0 = bm + warpM * 64 + f * 16 + qr;
        int r1 = r0 + 8;
        #pragma unroll
        for (int g = 0; g < 4; g++) {
            int c0 = bn + warpN * 32 + g * 8 + 2 * qc;
            if (r0 < M) {
                *reinterpret_cast<float2*>(Cp + (size_t)r0 * N + c0) =
                    make_float2(acc[f][g][0], acc[f][g][1]);
                csum[g][0] += acc[f][g][0]; csq[g][0] += acc[f][g][0] * acc[f][g][0];
                csum[g][1] += acc[f][g][1]; csq[g][1] += acc[f][g][1] * acc[f][g][1];
            }
            if (r1 < M) {
                *reinterpret_cast<float2*>(Cp + (size_t)r1 * N + c0) =
                    make_float2(acc[f][g][2], acc[f][g][3]);
                csum[g][0] += acc[f][g][2]; csq[g][0] += acc[f][g][2] * acc[f][g][2];
                csum[g][1] += acc[f][g][3]; csq[g][1] += acc[f][g][3] * acc[f][g][3];
            }
        }
    }
    __syncthreads();
    #pragma unroll
    for (int g = 0; g < 4; g++) {
        int cl = warpN * 32 + g * 8 + 2 * qc;
        atomicAdd(&s_sum[cl], csum[g][0]);     atomicAdd(&s_sq[cl], csq[g][0]);
        atomicAdd(&s_sum[cl + 1], csum[g][1]); atomicAdd(&s_sq[cl + 1], csq[g][1]);
    }
    __syncthreads();
    for (int c = tid; c < 128; c += 256) {
        atomicAdd(&st[bn + c],     s_sum[c]);
        atomicAdd(&st[N + bn + c], s_sq[c]);
    }
}

// ---------------- BN + ReLU (final output only) ----------------
__global__ void bnrelu_kernel(const float* __restrict__ Y, float* __restrict__ Z,
                              int M, int C, const float* __restrict__ st,
                              const float* __restrict__ G, const float* __restrict__ B) {
    size_t total = (size_t)M * C;
    size_t stride = (size_t)gridDim.x * blockDim.x;
    float invM = 1.0f / (float)M;
    for (size_t i = (size_t)blockIdx.x * blockDim.x + threadIdx.x; i < total; i += stride) {
        int c = (int)(i % C);
        float m = st[c] * invM;
        float v = st[C + c] * invM - m * m;
        float sc = rsqrtf(fmaxf(v, 0.0f) + 1e-5f);
        float z = (Y[i] - m) * sc * G[c] + B[c];
        Z[i] = fmaxf(z, 0.0f);
    }
}

// ---------------- alignment (matches jitted reference bit-exactly) ----------------
__device__ __forceinline__ int lower_bound_i32(const int* __restrict__ a, int n, int key) {
    int lo = 0, hi = n;
    while (lo < hi) {
        int mid = (lo + hi) >> 1;
        if (a[mid] < key) lo = mid + 1; else hi = mid;
    }
    return lo;
}

__global__ void align_kernel(const int* __restrict__ uc1, int M1,
                             const int* __restrict__ keys0, int M0,
                             const int* __restrict__ keys2, int M2) {
    int i = blockIdx.x * blockDim.x + threadIdx.x;
    if (i >= M1) return;
    int b  = uc1[4 * i + 0];
    int cx = uc1[4 * i + 1];
    int cy = uc1[4 * i + 2];
    int cz = uc1[4 * i + 3];
    float rx = __fadd_rn(__fmul_rn(__fadd_rn((float)cx, 0.5f), 0.2f), -50.0f);
    float ry = __fadd_rn(__fmul_rn(__fadd_rn((float)cy, 0.5f), 0.2f), -50.0f);
    float rz = __fadd_rn(__fmul_rn(__fadd_rn((float)cz, 0.5f), 0.2f), -3.0f);
    float dx = __fsub_rn(rx, -50.0f);
    float dy = __fsub_rn(ry, -50.0f);
    float dz = __fsub_rn(rz, -3.0f);
    {
        int ix = (int)floorf(__fmul_rn(dx, 10.0f)); ix = min(max(ix, 0), 999);
        int iy = (int)floorf(__fmul_rn(dy, 10.0f)); iy = min(max(iy, 0), 999);
        int iz = (int)floorf(__fmul_rn(dz, 10.0f)); iz = min(max(iz, 0), 59);
        int k = b * 1000000000 + ix * 1000000 + iy * 1000 + iz;
        int lo = lower_bound_i32(keys0, M0, k);
        int idx = min(lo, M0 - 1); if (idx < 0) idx = 0;
        g_idx0[i] = (keys0[idx] == k) ? idx : -1;
    }
    {
        int ix = (int)floorf(__fmul_rn(dx, 2.5f)); ix = min(max(ix, 0), 249);
        int iy = (int)floorf(__fmul_rn(dy, 2.5f)); iy = min(max(iy, 0), 249);
        int iz = (int)floorf(__fmul_rn(dz, 2.5f)); iz = min(max(iz, 0), 14);
        int k = b * 1000000000 + ix * 1000000 + iy * 1000 + iz;
        int lo = lower_bound_i32(keys2, M2, k);
        int idx = min(lo, M2 - 1); if (idx < 0) idx = 0;
        g_idx2[i] = (keys2[idx] == k) ? idx : -1;
    }
}

// ---------------- host orchestration ----------------
extern "C" void kernel_launch(void* const* d_in, const int* in_sizes, int n_in,
                              void* d_out, int out_size) {
    (void)n_in; (void)out_size;
    const float* points = (const float*)d_in[0];
    const float* W1 = (const float*)d_in[1];
    const float* G1 = (const float*)d_in[2];
    const float* B1 = (const float*)d_in[3];
    const float* W2 = (const float*)d_in[4];
    const float* G2 = (const float*)d_in[5];
    const float* B2 = (const float*)d_in[6];
    const float* W3 = (const float*)d_in[7];
    const float* G3 = (const float*)d_in[8];
    const float* B3 = (const float*)d_in[9];
    const float* Wf = (const float*)d_in[10];
    const float* Gf = (const float*)d_in[11];
    const float* Bf = (const float*)d_in[12];
    const int* inv0 = (const int*)d_in[13];
    const int* inv1 = (const int*)d_in[14];
    const int* inv2 = (const int*)d_in[15];
    const int* keys0 = (const int*)d_in[16];
    const int* keys2 = (const int*)d_in[17];
    const int* uc1   = (const int*)d_in[18];

    int N  = in_sizes[0] / 4;
    int M0 = in_sizes[16];
    int M2 = in_sizes[17];
    int M1 = in_sizes[18] / 4;
    int maxM = M0 > M1 ? M0 : M1; if (M2 > maxM) maxM = M2;
    int3 Ms3 = make_int3(M0, M1, M2);

    float *t64, *t128, *feat, *y, *stats, *bnp;
    cudaGetSymbolAddress((void**)&t64,  g_t64);
    cudaGetSymbolAddress((void**)&t128, g_t128);
    cudaGetSymbolAddress((void**)&feat, g_feat);
    cudaGetSymbolAddress((void**)&y,    g_y);
    cudaGetSymbolAddress((void**)&stats, g_stats);
    cudaGetSymbolAddress((void**)&bnp,   g_bnp);

    zero_kernel<<<2048, 256>>>();
    wconv_kernel<<<(WTOT + 255) / 256, 256>>>(W2, W3, Wf);
    scatter_kernel<<<(N + 255) / 256, 256>>>(points, inv0, inv1, inv2, N);
    align_kernel<<<(M1 + 255) / 256, 256>>>(uc1, M1, keys0, M0, keys2, M2);

    // Layer 1 fused (mean + K=4 GEMM + stats)
    l1_kernel<<<dim3((maxM + 511) / 512, 3), 256>>>(W1, Ms3);
    finalize_kernel<<<dim3(1, 3), 64>>>(stats, bnp, G1, B1, 64, Ms3);
    xform_kernel<<<dim3(512, 3), 256>>>(t64, 64, Ms3, bnp);

    int gy = (maxM + 127) / 128;

    // Layer 2: [M,64] -> [M,128]
    mma_gemm<1><<<dim3(1, gy, 3), 256>>>(64, WOFF2, 128 * 64,
                                         t128, (size_t)MAXM * 128, Ms3, 128,
                                         stats + 4608);
    finalize_kernel<<<dim3(1, 3), 128>>>(stats + 4608, bnp + 4608, G2, B2, 128, Ms3);
    xform_kernel<<<dim3(512, 3), 256>>>(t128, 128, Ms3, bnp + 4608);

    // Layer 3: [M,128] -> [M,256]
    mma_gemm<1><<<dim3(2, gy, 3), 256>>>(128, WOFF3, 256 * 128,
                                         feat, (size_t)MAXM * 256, Ms3, 256,
                                         stats + 9216);
    finalize_kernel<<<dim3(1, 3), 256>>>(stats + 9216, bnp + 9216, G3, B3, 256, Ms3);
    xform_kernel<<<dim3(512, 3), 256>>>(feat, 256, Ms3, bnp + 9216);

    // Final: gather [M1,768] -> [M1,256]
    mma_gemm<2><<<dim3(2, (M1 + 127) / 128, 1), 256>>>(768, WOFFF, 0,
                                                       y, 0, Ms3, 256,
                                                       stats + 13824);

    bnrelu_kernel<<<4096, 256>>>(y, (float*)d_out, M1, 256, stats + 13824, Gf, Bf);
}

// round 15
// speedup vs baseline: 1.1505x; 1.1470x over previous
#include <cuda_runtime.h>
#include <cuda_fp16.h>
#include <math.h>
#include <stdint.h>

#define MAXM 200000

// weight plane offsets (elements)
#define WOFF2 0
#define WOFF3 24576          // 3*128*64
#define WOFFF 122880         // WOFF3 + 3*256*128
#define WTOT  319488         // WOFFF + 256*768

// ---------------- static device scratch ----------------
__device__ float g_acc[3 * MAXM * 5];
__device__ float g_t64[(size_t)3 * MAXM * 64];    // layer1 out, pre-BN fp32
__device__ float g_t128[(size_t)3 * MAXM * 128];  // layer2 out, pre-BN fp32
__device__ float g_feat[(size_t)3 * MAXM * 256];  // layer3 out, pre-BN fp32
__device__ float g_y[(size_t)MAXM * 256];         // final pre-BN
__device__ float g_stats[10 * 1536];
__device__ float g_bnp[10 * 1536];
__device__ int   g_idx0[MAXM];
__device__ int   g_idx2[MAXM];
__device__ __half g_wh[WTOT];                     // weight hi plane (fp16)
__device__ __half g_wl[WTOT];                     // weight lo plane (fp16 residual)
__device__ __half g_a16[(size_t)3 * MAXM * 256];  // activation fp16 plane (post-BN+ReLU)

// ---------------- zero scratch ----------------
__global__ void zero_kernel() {
    const size_t n1 = (size_t)3 * MAXM * 5;
    const size_t total = n1 + 10 * 1536;
    const size_t stride = (size_t)gridDim.x * blockDim.x;
    for (size_t i = (size_t)blockIdx.x * blockDim.x + threadIdx.x; i < total; i += stride) {
        if (i < n1) g_acc[i] = 0.0f;
        else        g_stats[i - n1] = 0.0f;
    }
}

// ---------------- weight pre-conversion to split fp16 ----------------
__global__ void wconv_kernel(const float* __restrict__ W2, const float* __restrict__ W3,
                             const float* __restrict__ Wf) {
    int i = blockIdx.x * blockDim.x + threadIdx.x;
    if (i >= WTOT) return;
    float v;
    if (i < WOFF3) v = W2[i];
    else if (i < WOFFF) v = W3[i - WOFF3];
    else v = Wf[i - WOFFF];
    __half h = __float2half_rn(v);
    g_wh[i] = h;
    g_wl[i] = __float2half_rn(v - __half2float(h));
}

// ---------------- scatter ----------------
__global__ void scatter_kernel(const float* __restrict__ pts,
                               const int* __restrict__ inv0,
                               const int* __restrict__ inv1,
                               const int* __restrict__ inv2, int N) {
    int i = blockIdx.x * blockDim.x + threadIdx.x;
    if (i >= N) return;
    float4 p = reinterpret_cast<const float4*>(pts)[i];
    int m0 = inv0[i], m1 = inv1[i], m2 = inv2[i];
    float* a0 = g_acc + (size_t)m0 * 5;
    float* a1 = g_acc + (size_t)MAXM * 5 + (size_t)m1 * 5;
    float* a2 = g_acc + (size_t)2 * MAXM * 5 + (size_t)m2 * 5;
    atomicAdd(a0 + 0, p.x); atomicAdd(a0 + 1, p.y); atomicAdd(a0 + 2, p.z); atomicAdd(a0 + 3, p.w); atomicAdd(a0 + 4, 1.0f);
    atomicAdd(a1 + 0, p.x); atomicAdd(a1 + 1, p.y); atomicAdd(a1 + 2, p.z); atomicAdd(a1 + 3, p.w); atomicAdd(a1 + 4, 1.0f);
    atomicAdd(a2 + 0, p.x); atomicAdd(a2 + 1, p.y); atomicAdd(a2 + 2, p.z); atomicAdd(a2 + 3, p.w); atomicAdd(a2 + 4, 1.0f);
}

// ---------------- fused mean + layer1 (K=4 -> 64) + column stats ----------------
__global__ void l1_kernel(const float* __restrict__ W1, int3 Ms) {
    int s = blockIdx.y;
    int M = (s == 0) ? Ms.x : (s == 1) ? Ms.y : Ms.z;
    __shared__ float Wsm[256];
    __shared__ float s_sum[64], s_sq[64];
    int tid = threadIdx.x;
    Wsm[tid] = W1[s * 256 + tid];
    if (tid < 64) { s_sum[tid] = 0.0f; s_sq[tid] = 0.0f; }
    __syncthreads();
    int lane = tid & 31, w = tid >> 5;
    int c0 = lane * 2;
    float w00 = Wsm[c0 * 4 + 0], w01 = Wsm[c0 * 4 + 1], w02 = Wsm[c0 * 4 + 2], w03 = Wsm[c0 * 4 + 3];
    float w10 = Wsm[c0 * 4 + 4], w11 = Wsm[c0 * 4 + 5], w12 = Wsm[c0 * 4 + 6], w13 = Wsm[c0 * 4 + 7];
    const float* acc = g_acc + (size_t)s * MAXM * 5;
    float* out = g_t64 + (size_t)s * MAXM * 64;
    float sum0 = 0, sq0 = 0, sum1 = 0, sq1 = 0;
    int base = blockIdx.x * 512;
    if (base >= M) return;
    int lim = min(base + 512, M);
    for (int r = base + w; r < lim; r += 8) {
        const float* a = acc + (size_t)r * 5;
        float cnt = fmaxf(__ldg(a + 4), 1.0f);
        float x0 = __ldg(a + 0) / cnt, x1 = __ldg(a + 1) / cnt;
        float x2 = __ldg(a + 2) / cnt, x3 = __ldg(a + 3) / cnt;
        float o0 = x0 * w00 + x1 * w01 + x2 * w02 + x3 * w03;
        float o1 = x0 * w10 + x1 * w11 + x2 * w12 + x3 * w13;
        *reinterpret_cast<float2*>(out + (size_t)r * 64 + c0) = make_float2(o0, o1);
        sum0 += o0; sq0 += o0 * o0; sum1 += o1; sq1 += o1 * o1;
    }
    atomicAdd(&s_sum[c0], sum0);     atomicAdd(&s_sq[c0], sq0);
    atomicAdd(&s_sum[c0 + 1], sum1); atomicAdd(&s_sq[c0 + 1], sq1);
    __syncthreads();
    if (tid < 64) {
        atomicAdd(&g_stats[s * 1536 + tid], s_sum[tid]);
        atomicAdd(&g_stats[s * 1536 + 64 + tid], s_sq[tid]);
    }
}

// ---------------- finalize: raw sum/sumsq -> (scale, shift) ----------------
__global__ void finalize_kernel(const float* __restrict__ st, float* __restrict__ bnp,
                                const float* __restrict__ G, const float* __restrict__ Bb,
                                int C, int3 Ms) {
    int s = blockIdx.y;
    int c = blockIdx.x * blockDim.x + threadIdx.x;
    if (c >= C) return;
    float M = (float)((s == 0) ? Ms.x : (s == 1) ? Ms.y : Ms.z);
    const float* stb = st + (size_t)s * 1536;
    float m = stb[c] / M;
    float v = stb[C + c] / M - m * m;
    float rs = rsqrtf(fmaxf(v, 0.0f) + 1e-5f);
    float sc = rs * G[s * C + c];
    float sh = Bb[s * C + c] - m * sc;
    bnp[(size_t)s * 1536 + c] = sc;
    bnp[(size_t)s * 1536 + C + c] = sh;
}

// ---------------- xform: pre-BN fp32 -> post-BN+ReLU fp16 plane ----------------
__global__ void xform_kernel(const float* __restrict__ X, int K, int3 Ms,
                             const float* __restrict__ bnp) {
    int s = blockIdx.y;
    int M = (s == 0) ? Ms.x : (s == 1) ? Ms.y : Ms.z;
    const float* Xs = X + (size_t)s * MAXM * K;
    const float* sc = bnp + (size_t)s * 1536;
    const float* sh = sc + K;
    __half* as = g_a16 + (size_t)s * MAXM * K;
    int kc = K >> 3;
    size_t total = (size_t)M * kc;
    size_t stride = (size_t)gridDim.x * blockDim.x;
    for (size_t idx = (size_t)blockIdx.x * blockDim.x + threadIdx.x; idx < total; idx += stride) {
        size_t m = idx / kc;
        int c8 = (int)(idx - m * kc) * 8;
        const float* p = Xs + m * K + c8;
        float4 v0 = *reinterpret_cast<const float4*>(p);
        float4 v1 = *reinterpret_cast<const float4*>(p + 4);
        float vv[8] = {v0.x, v0.y, v0.z, v0.w, v1.x, v1.y, v1.z, v1.w};
        __half hh[8];
        #pragma unroll
        for (int c = 0; c < 8; c++) {
            float t = fmaxf(vv[c] * __ldg(sc + c8 + c) + __ldg(sh + c8 + c), 0.0f);
            hh[c] = __float2half_rn(t);
        }
        *reinterpret_cast<uint4*>(as + m * K + c8) = *reinterpret_cast<uint4*>(hh);
    }
}

// ---------------- mma helpers ----------------
__device__ __forceinline__ uint32_t smem_u32(const void* p) {
    uint32_t a;
    asm("{ .reg .u64 t; cvta.to.shared.u64 t, %1; cvt.u32.u64 %0, t; }" : "=r"(a) : "l"(p));
    return a;
}
__device__ __forceinline__ void mma_fp16(float* d, const uint32_t* a, const uint32_t* b) {
    asm volatile(
        "mma.sync.aligned.m16n8k16.row.col.f32.f16.f16.f32 "
        "{%0,%1,%2,%3}, {%4,%5,%6,%7}, {%8,%9}, {%0,%1,%2,%3};"
        : "+f"(d[0]), "+f"(d[1]), "+f"(d[2]), "+f"(d[3])
        : "r"(a[0]), "r"(a[1]), "r"(a[2]), "r"(a[3]), "r"(b[0]), "r"(b[1]));
}
__device__ __forceinline__ void ldsm_x4(uint32_t* r, uint32_t addr) {
    asm volatile("ldmatrix.sync.aligned.m8n8.x4.shared.b16 {%0,%1,%2,%3}, [%4];"
                 : "=r"(r[0]), "=r"(r[1]), "=r"(r[2]), "=r"(r[3]) : "r"(addr));
}
__device__ __forceinline__ void cp_async16(uint32_t dst, const void* src) {
    asm volatile("cp.async.cg.shared.global [%0], [%1], 16;" :: "r"(dst), "l"(src) : "memory");
}
__device__ __forceinline__ void cp_async16z(uint32_t dst, const void* src, uint32_t srcsz) {
    asm volatile("cp.async.cg.shared.global [%0], [%1], 16, %2;"
                 :: "r"(dst), "l"(src), "r"(srcsz) : "memory");
}
__device__ __forceinline__ void cp_commit() {
    asm volatile("cp.async.commit_group;" ::: "memory");
}
__device__ __forceinline__ void cp_wait_all() {
    asm volatile("cp.async.wait_group 0;" ::: "memory");
}

// ---------------- fp16 2-term tensor GEMM ----------------
// D = A * (Wh + Wl): A single fp16 plane, W split fp16 hi/lo (products exact, f32 accum).
// CTA 128x128, 8 warps (warp tile 64x32), K-chunk 32, double buffered, pure cp.async.
// Smem rows 64B data + 16B pad (80B stride, conflict-free ldmatrix).
// MODE 1: A rows contiguous in plane. MODE 2: gathered rows (768-K concat).
template<int MODE>
__global__ void __launch_bounds__(256, 2)
mma_gemm(int K, int woff, size_t Wstr,
         float* __restrict__ Cbase, size_t Cstr,
         int3 Ms, int N,
         float* __restrict__ stbase) {
    constexpr int RS = 20;               // smem row stride in u32 (80B)
    int s = blockIdx.z;
    int M = (MODE == 2) ? Ms.y : ((s == 0) ? Ms.x : (s == 1) ? Ms.y : Ms.z);
    int bm = blockIdx.y * 128;
    if (bm >= M) return;
    int bn = blockIdx.x * 128;

    const __half* Ap = g_a16 + (size_t)s * MAXM * K;
    const __half* Wh = g_wh + woff + (size_t)s * Wstr;
    const __half* Wl = g_wl + woff + (size_t)s * Wstr;
    float* Cp = Cbase + (size_t)s * Cstr;
    float* st = stbase + (size_t)s * 1536;

    __shared__ uint32_t sA[2][128 * RS];
    __shared__ uint32_t sBh[2][128 * RS], sBl[2][128 * RS];
    __shared__ float s_sum[128], s_sq[128];

    int tid = threadIdx.x;
    int lane = tid & 31, warp = tid >> 5;
    int warpM = warp & 1, warpN = warp >> 1;

    for (int c = tid; c < 128; c += 256) { s_sum[c] = 0.0f; s_sq[c] = 0.0f; }

    uint32_t baseA = smem_u32(sA[0]);
    uint32_t baseBh = smem_u32(sBh[0]), baseBl = smem_u32(sBl[0]);

    float acc[4][4][4];
    #pragma unroll
    for (int f = 0; f < 4; f++)
        #pragma unroll
        for (int g = 0; g < 4; g++)
            #pragma unroll
            for (int r = 0; r < 4; r++) acc[f][g][r] = 0.0f;

    int a_row = lane & 15;
    int a_koff = (lane & 16) ? 16 : 0;
    // B x4 addressing: matrices 0,1 = n-group gp*2 (k0-7, k8-15); 2,3 = n-group gp*2+1
    int b4_row = (lane & 7) + ((lane & 16) ? 8 : 0);
    int b4_koff = (lane & 8) ? 16 : 0;

    auto issueAB = [&](int t, int buf) {
        int tk = t * 32;
        uint32_t a0 = baseA + (uint32_t)buf * (128 * RS * 4);
        uint32_t bh0 = baseBh + (uint32_t)buf * (128 * RS * 4);
        uint32_t bl0 = baseBl + (uint32_t)buf * (128 * RS * 4);
        #pragma unroll
        for (int i = 0; i < 2; i++) {
            int v = tid + i * 256;
            int r = v >> 2, q = v & 3;
            int gk = tk + q * 8;
            uint32_t dst = (uint32_t)(r * 80 + q * 16);
            // A row r
            if (MODE == 1) {
                int gm = bm + r;
                cp_async16(a0 + dst, Ap + (size_t)gm * K + gk);
            } else {
                int gm = bm + r;
                int seg = gk >> 8, off = gk & 255;
                int j = -1;
                if (gm < M) {
                    if (seg == 0) j = g_idx0[gm];
                    else if (seg == 1) j = gm;
                    else j = g_idx2[gm];
                }
                uint32_t ok = (j >= 0) ? 16u : 0u;
                size_t srow = (size_t)seg * MAXM + (j >= 0 ? j : 0);
                cp_async16z(a0 + dst, g_a16 + srow * 256 + off, ok);
            }
            // B row r (both planes)
            int gn = bn + r;
            cp_async16(bh0 + dst, Wh + (size_t)gn * K + gk);
            cp_async16(bl0 + dst, Wl + (size_t)gn * K + gk);
        }
        cp_commit();
    };

    int nch = K / 32;
    issueAB(0, 0);

    for (int t = 0; t < nch; t++) {
        cp_wait_all();
        __syncthreads();
        if (t + 1 < nch) issueAB(t + 1, (t + 1) & 1);
        int buf = t & 1;
        uint32_t off0 = (uint32_t)buf * (128 * RS * 4);

        #pragma unroll
        for (int kk = 0; kk < 32; kk += 16) {
            uint32_t bh[4][2], bl[4][2];
            #pragma unroll
            for (int gp = 0; gp < 2; gp++) {
                int n0 = warpN * 32 + gp * 16;
                uint32_t off = off0 + (uint32_t)((n0 + b4_row) * 80 + kk * 2 + b4_koff);
                uint32_t tm[4];
                ldsm_x4(tm, baseBh + off);
                bh[2 * gp][0] = tm[0]; bh[2 * gp][1] = tm[1];
                bh[2 * gp + 1][0] = tm[2]; bh[2 * gp + 1][1] = tm[3];
                ldsm_x4(tm, baseBl + off);
                bl[2 * gp][0] = tm[0]; bl[2 * gp][1] = tm[1];
                bl[2 * gp + 1][0] = tm[2]; bl[2 * gp + 1][1] = tm[3];
            }
            #pragma unroll
            for (int f = 0; f < 4; f++) {
                int m0 = warpM * 64 + f * 16;
                uint32_t off = off0 + (uint32_t)((m0 + a_row) * 80 + kk * 2 + a_koff);
                uint32_t av[4];
                ldsm_x4(av, baseA + off);
                #pragma unroll
                for (int g = 0; g < 4; g++) {
                    mma_fp16(acc[f][g], av, bh[g]);
                    mma_fp16(acc[f][g], av, bl[g]);
                }
            }
        }
    }

    // ---- epilogue: store C + fused column stats ----
    float csum[4][2], csq[4][2];
    #pragma unroll
    for (int g = 0; g < 4; g++) { csum[g][0] = csum[g][1] = 0.f; csq[g][0] = csq[g][1] = 0.f; }

    int qr = lane >> 2, qc = lane & 3;
    #pragma unroll
    for (int f = 0; f < 4; f++) {
        int r0 = bm + warpM * 64 + f * 16 + qr;
        int r1 = r0 + 8;
        #pragma unroll
        for (int g = 0; g < 4; g++) {
            int c0 = bn + warpN * 32 + g * 8 + 2 * qc;
            if (r0 < M) {
                *reinterpret_cast<float2*>(Cp + (size_t)r0 * N + c0) =
                    make_float2(acc[f][g][0], acc[f][g][1]);
                csum[g][0] += acc[f][g][0]; csq[g][0] += acc[f][g][0] * acc[f][g][0];
                csum[g][1] += acc[f][g][1]; csq[g][1] += acc[f][g][1] * acc[f][g][1];
            }
            if (r1 < M) {
                *reinterpret_cast<float2*>(Cp + (size_t)r1 * N + c0) =
                    make_float2(acc[f][g][2], acc[f][g][3]);
                csum[g][0] += acc[f][g][2]; csq[g][0] += acc[f][g][2] * acc[f][g][2];
                csum[g][1] += acc[f][g][3]; csq[g][1] += acc[f][g][3] * acc[f][g][3];
            }
        }
    }
    __syncthreads();
    #pragma unroll
    for (int g = 0; g < 4; g++) {
        int cl = warpN * 32 + g * 8 + 2 * qc;
        atomicAdd(&s_sum[cl], csum[g][0]);     atomicAdd(&s_sq[cl], csq[g][0]);
        atomicAdd(&s_sum[cl + 1], csum[g][1]); atomicAdd(&s_sq[cl + 1], csq[g][1]);
    }
    __syncthreads();
    for (int c = tid; c < 128; c += 256) {
        atomicAdd(&st[bn + c],     s_sum[c]);
        atomicAdd(&st[N + bn + c], s_sq[c]);
    }
}

// ---------------- BN + ReLU (final output only) ----------------
__global__ void bnrelu_kernel(const float* __restrict__ Y, float* __restrict__ Z,
                              int M, int C, const float* __restrict__ st,
                              const float* __restrict__ G, const float* __restrict__ B) {
    size_t total = (size_t)M * C;
    size_t stride = (size_t)gridDim.x * blockDim.x;
    float invM = 1.0f / (float)M;
    for (size_t i = (size_t)blockIdx.x * blockDim.x + threadIdx.x; i < total; i += stride) {
        int c = (int)(i % C);
        float m = st[c] * invM;
        float v = st[C + c] * invM - m * m;
        float sc = rsqrtf(fmaxf(v, 0.0f) + 1e-5f);
        float z = (Y[i] - m) * sc * G[c] + B[c];
        Z[i] = fmaxf(z, 0.0f);
    }
}

// ---------------- alignment (matches jitted reference bit-exactly) ----------------
__device__ __forceinline__ int lower_bound_i32(const int* __restrict__ a, int n, int key) {
    int lo = 0, hi = n;
    while (lo < hi) {
        int mid = (lo + hi) >> 1;
        if (a[mid] < key) lo = mid + 1; else hi = mid;
    }
    return lo;
}

__global__ void align_kernel(const int* __restrict__ uc1, int M1,
                             const int* __restrict__ keys0, int M0,
                             const int* __restrict__ keys2, int M2) {
    int i = blockIdx.x * blockDim.x + threadIdx.x;
    if (i >= M1) return;
    int b  = uc1[4 * i + 0];
    int cx = uc1[4 * i + 1];
    int cy = uc1[4 * i + 2];
    int cz = uc1[4 * i + 3];
    float rx = __fadd_rn(__fmul_rn(__fadd_rn((float)cx, 0.5f), 0.2f), -50.0f);
    float ry = __fadd_rn(__fmul_rn(__fadd_rn((float)cy, 0.5f), 0.2f), -50.0f);
    float rz = __fadd_rn(__fmul_rn(__fadd_rn((float)cz, 0.5f), 0.2f), -3.0f);
    float dx = __fsub_rn(rx, -50.0f);
    float dy = __fsub_rn(ry, -50.0f);
    float dz = __fsub_rn(rz, -3.0f);
    {
        int ix = (int)floorf(__fmul_rn(dx, 10.0f)); ix = min(max(ix, 0), 999);
        int iy = (int)floorf(__fmul_rn(dy, 10.0f)); iy = min(max(iy, 0), 999);
        int iz = (int)floorf(__fmul_rn(dz, 10.0f)); iz = min(max(iz, 0), 59);
        int k = b * 1000000000 + ix * 1000000 + iy * 1000 + iz;
        int lo = lower_bound_i32(keys0, M0, k);
        int idx = min(lo, M0 - 1); if (idx < 0) idx = 0;
        g_idx0[i] = (keys0[idx] == k) ? idx : -1;
    }
    {
        int ix = (int)floorf(__fmul_rn(dx, 2.5f)); ix = min(max(ix, 0), 249);
        int iy = (int)floorf(__fmul_rn(dy, 2.5f)); iy = min(max(iy, 0), 249);
        int iz = (int)floorf(__fmul_rn(dz, 2.5f)); iz = min(max(iz, 0), 14);
        int k = b * 1000000000 + ix * 1000000 + iy * 1000 + iz;
        int lo = lower_bound_i32(keys2, M2, k);
        int idx = min(lo, M2 - 1); if (idx < 0) idx = 0;
        g_idx2[i] = (keys2[idx] == k) ? idx : -1;
    }
}

// ---------------- host orchestration ----------------
extern "C" void kernel_launch(void* const* d_in, const int* in_sizes, int n_in,
                              void* d_out, int out_size) {
    (void)n_in; (void)out_size;
    const float* points = (const float*)d_in[0];
    const float* W1 = (const float*)d_in[1];
    const float* G1 = (const float*)d_in[2];
    const float* B1 = (const float*)d_in[3];
    const float* W2 = (const float*)d_in[4];
    const float* G2 = (const float*)d_in[5];
    const float* B2 = (const float*)d_in[6];
    const float* W3 = (const float*)d_in[7];
    const float* G3 = (const float*)d_in[8];
    const float* B3 = (const float*)d_in[9];
    const float* Wf = (const float*)d_in[10];
    const float* Gf = (const float*)d_in[11];
    const float* Bf = (const float*)d_in[12];
    const int* inv0 = (const int*)d_in[13];
    const int* inv1 = (const int*)d_in[14];
    const int* inv2 = (const int*)d_in[15];
    const int* keys0 = (const int*)d_in[16];
    const int* keys2 = (const int*)d_in[17];
    const int* uc1   = (const int*)d_in[18];

    int N  = in_sizes[0] / 4;
    int M0 = in_sizes[16];
    int M2 = in_sizes[17];
    int M1 = in_sizes[18] / 4;
    int maxM = M0 > M1 ? M0 : M1; if (M2 > maxM) maxM = M2;
    int3 Ms3 = make_int3(M0, M1, M2);

    float *t64, *t128, *feat, *y, *stats, *bnp;
    cudaGetSymbolAddress((void**)&t64,  g_t64);
    cudaGetSymbolAddress((void**)&t128, g_t128);
    cudaGetSymbolAddress((void**)&feat, g_feat);
    cudaGetSymbolAddress((void**)&y,    g_y);
    cudaGetSymbolAddress((void**)&stats, g_stats);
    cudaGetSymbolAddress((void**)&bnp,   g_bnp);

    zero_kernel<<<2048, 256>>>();
    wconv_kernel<<<(WTOT + 255) / 256, 256>>>(W2, W3, Wf);
    scatter_kernel<<<(N + 255) / 256, 256>>>(points, inv0, inv1, inv2, N);
    align_kernel<<<(M1 + 255) / 256, 256>>>(uc1, M1, keys0, M0, keys2, M2);

    // Layer 1 fused (mean + K=4 GEMM + stats)
    l1_kernel<<<dim3((maxM + 511) / 512, 3), 256>>>(W1, Ms3);
    finalize_kernel<<<dim3(1, 3), 64>>>(stats, bnp, G1, B1, 64, Ms3);
    xform_kernel<<<dim3(512, 3), 256>>>(t64, 64, Ms3, bnp);

    int gy = (maxM + 127) / 128;

    // Layer 2: [M,64] -> [M,128]
    mma_gemm<1><<<dim3(1, gy, 3), 256>>>(64, WOFF2, 128 * 64,
                                         t128, (size_t)MAXM * 128, Ms3, 128,
                                         stats + 4608);
    finalize_kernel<<<dim3(1, 3), 128>>>(stats + 4608, bnp + 4608, G2, B2, 128, Ms3);
    xform_kernel<<<dim3(512, 3), 256>>>(t128, 128, Ms3, bnp + 4608);

    // Layer 3: [M,128] -> [M,256]
    mma_gemm<1><<<dim3(2, gy, 3), 256>>>(128, WOFF3, 256 * 128,
                                         feat, (size_t)MAXM * 256, Ms3, 256,
                                         stats + 9216);
    finalize_kernel<<<dim3(1, 3), 256>>>(stats + 9216, bnp + 9216, G3, B3, 256, Ms3);
    xform_kernel<<<dim3(512, 3), 256>>>(feat, 256, Ms3, bnp + 9216);

    // Final: gather [M1,768] -> [M1,256]
    mma_gemm<2><<<dim3(2, (M1 + 127) / 128, 1), 256>>>(768, WOFFF, 0,
                                                       y, 0, Ms3, 256,
                                                       stats + 13824);

    bnrelu_kernel<<<4096, 256>>>(y, (float*)d_out, M1, 256, stats + 13824, Gf, Bf);
}

// round 16
// speedup vs baseline: 1.2127x; 1.0541x over previous
#include <cuda_runtime.h>
#include <cuda_fp16.h>
#include <math.h>
#include <stdint.h>

#define MAXM 200000

// weight plane offsets (elements)
#define WOFF2 0
#define WOFF3 24576          // 3*128*64
#define WOFFF 122880         // WOFF3 + 3*256*128
#define WTOT  319488         // WOFFF + 256*768

// ---------------- static device scratch ----------------
__device__ float g_acc[3 * MAXM * 5];
__device__ float g_t64[(size_t)3 * MAXM * 64];    // layer1 out, pre-BN fp32
__device__ float g_t128[(size_t)3 * MAXM * 128];  // layer2 out, pre-BN fp32
__device__ float g_feat[(size_t)3 * MAXM * 256];  // layer3 out, pre-BN fp32
__device__ float g_y[(size_t)MAXM * 256];         // final pre-BN
__device__ float g_stats[10 * 1536];
__device__ float g_bnp[10 * 1536];
__device__ int   g_idx0[MAXM];
__device__ int   g_idx2[MAXM];
__device__ int   g_perm[MAXM];                    // matched-seg0 rows first
__device__ int   g_cnt[2];
__device__ __half g_wh[WTOT];                     // weight hi plane (fp16)
__device__ __half g_wl[WTOT];                     // weight lo plane (fp16 residual)
__device__ __half g_a16[(size_t)3 * MAXM * 256];  // activation fp16 plane (post-BN+ReLU)

// ---------------- zero scratch ----------------
__global__ void zero_kernel() {
    const size_t n1 = (size_t)3 * MAXM * 5;
    const size_t total = n1 + 10 * 1536;
    const size_t stride = (size_t)gridDim.x * blockDim.x;
    size_t i0 = (size_t)blockIdx.x * blockDim.x + threadIdx.x;
    if (i0 == 0) { g_cnt[0] = 0; g_cnt[1] = 0; }
    for (size_t i = i0; i < total; i += stride) {
        if (i < n1) g_acc[i] = 0.0f;
        else        g_stats[i - n1] = 0.0f;
    }
}

// ---------------- weight pre-conversion to split fp16 ----------------
__global__ void wconv_kernel(const float* __restrict__ W2, const float* __restrict__ W3,
                             const float* __restrict__ Wf) {
    int i = blockIdx.x * blockDim.x + threadIdx.x;
    if (i >= WTOT) return;
    float v;
    if (i < WOFF3) v = W2[i];
    else if (i < WOFFF) v = W3[i - WOFF3];
    else v = Wf[i - WOFFF];
    __half h = __float2half_rn(v);
    g_wh[i] = h;
    g_wl[i] = __float2half_rn(v - __half2float(h));
}

// ---------------- scatter ----------------
__global__ void scatter_kernel(const float* __restrict__ pts,
                               const int* __restrict__ inv0,
                               const int* __restrict__ inv1,
                               const int* __restrict__ inv2, int N) {
    int i = blockIdx.x * blockDim.x + threadIdx.x;
    if (i >= N) return;
    float4 p = reinterpret_cast<const float4*>(pts)[i];
    int m0 = inv0[i], m1 = inv1[i], m2 = inv2[i];
    float* a0 = g_acc + (size_t)m0 * 5;
    float* a1 = g_acc + (size_t)MAXM * 5 + (size_t)m1 * 5;
    float* a2 = g_acc + (size_t)2 * MAXM * 5 + (size_t)m2 * 5;
    atomicAdd(a0 + 0, p.x); atomicAdd(a0 + 1, p.y); atomicAdd(a0 + 2, p.z); atomicAdd(a0 + 3, p.w); atomicAdd(a0 + 4, 1.0f);
    atomicAdd(a1 + 0, p.x); atomicAdd(a1 + 1, p.y); atomicAdd(a1 + 2, p.z); atomicAdd(a1 + 3, p.w); atomicAdd(a1 + 4, 1.0f);
    atomicAdd(a2 + 0, p.x); atomicAdd(a2 + 1, p.y); atomicAdd(a2 + 2, p.z); atomicAdd(a2 + 3, p.w); atomicAdd(a2 + 4, 1.0f);
}

// ---------------- fused mean + layer1 (K=4 -> 64) + column stats ----------------
__global__ void l1_kernel(const float* __restrict__ W1, int3 Ms) {
    int s = blockIdx.y;
    int M = (s == 0) ? Ms.x : (s == 1) ? Ms.y : Ms.z;
    __shared__ float Wsm[256];
    __shared__ float s_sum[64], s_sq[64];
    int tid = threadIdx.x;
    Wsm[tid] = W1[s * 256 + tid];
    if (tid < 64) { s_sum[tid] = 0.0f; s_sq[tid] = 0.0f; }
    __syncthreads();
    int lane = tid & 31, w = tid >> 5;
    int c0 = lane * 2;
    float w00 = Wsm[c0 * 4 + 0], w01 = Wsm[c0 * 4 + 1], w02 = Wsm[c0 * 4 + 2], w03 = Wsm[c0 * 4 + 3];
    float w10 = Wsm[c0 * 4 + 4], w11 = Wsm[c0 * 4 + 5], w12 = Wsm[c0 * 4 + 6], w13 = Wsm[c0 * 4 + 7];
    const float* acc = g_acc + (size_t)s * MAXM * 5;
    float* out = g_t64 + (size_t)s * MAXM * 64;
    float sum0 = 0, sq0 = 0, sum1 = 0, sq1 = 0;
    int base = blockIdx.x * 512;
    if (base >= M) return;
    int lim = min(base + 512, M);
    for (int r = base + w; r < lim; r += 8) {
        const float* a = acc + (size_t)r * 5;
        float cnt = fmaxf(__ldg(a + 4), 1.0f);
        float x0 = __ldg(a + 0) / cnt, x1 = __ldg(a + 1) / cnt;
        float x2 = __ldg(a + 2) / cnt, x3 = __ldg(a + 3) / cnt;
        float o0 = x0 * w00 + x1 * w01 + x2 * w02 + x3 * w03;
        float o1 = x0 * w10 + x1 * w11 + x2 * w12 + x3 * w13;
        *reinterpret_cast<float2*>(out + (size_t)r * 64 + c0) = make_float2(o0, o1);
        sum0 += o0; sq0 += o0 * o0; sum1 += o1; sq1 += o1 * o1;
    }
    atomicAdd(&s_sum[c0], sum0);     atomicAdd(&s_sq[c0], sq0);
    atomicAdd(&s_sum[c0 + 1], sum1); atomicAdd(&s_sq[c0 + 1], sq1);
    __syncthreads();
    if (tid < 64) {
        atomicAdd(&g_stats[s * 1536 + tid], s_sum[tid]);
        atomicAdd(&g_stats[s * 1536 + 64 + tid], s_sq[tid]);
    }
}

// ---------------- finalize: raw sum/sumsq -> (scale, shift) ----------------
__global__ void finalize_kernel(const float* __restrict__ st, float* __restrict__ bnp,
                                const float* __restrict__ G, const float* __restrict__ Bb,
                                int C, int3 Ms) {
    int s = blockIdx.y;
    int c = blockIdx.x * blockDim.x + threadIdx.x;
    if (c >= C) return;
    float M = (float)((s == 0) ? Ms.x : (s == 1) ? Ms.y : Ms.z);
    const float* stb = st + (size_t)s * 1536;
    float m = stb[c] / M;
    float v = stb[C + c] / M - m * m;
    float rs = rsqrtf(fmaxf(v, 0.0f) + 1e-5f);
    float sc = rs * G[s * C + c];
    float sh = Bb[s * C + c] - m * sc;
    bnp[(size_t)s * 1536 + c] = sc;
    bnp[(size_t)s * 1536 + C + c] = sh;
}

// ---------------- xform: pre-BN fp32 -> post-BN+ReLU fp16 plane ----------------
__global__ void xform_kernel(const float* __restrict__ X, int K, int3 Ms,
                             const float* __restrict__ bnp) {
    int s = blockIdx.y;
    int M = (s == 0) ? Ms.x : (s == 1) ? Ms.y : Ms.z;
    const float* Xs = X + (size_t)s * MAXM * K;
    const float* sc = bnp + (size_t)s * 1536;
    const float* sh = sc + K;
    __half* as = g_a16 + (size_t)s * MAXM * K;
    int kc = K >> 3;
    size_t total = (size_t)M * kc;
    size_t stride = (size_t)gridDim.x * blockDim.x;
    for (size_t idx = (size_t)blockIdx.x * blockDim.x + threadIdx.x; idx < total; idx += stride) {
        size_t m = idx / kc;
        int c8 = (int)(idx - m * kc) * 8;
        const float* p = Xs + m * K + c8;
        float4 v0 = *reinterpret_cast<const float4*>(p);
        float4 v1 = *reinterpret_cast<const float4*>(p + 4);
        float vv[8] = {v0.x, v0.y, v0.z, v0.w, v1.x, v1.y, v1.z, v1.w};
        __half hh[8];
        #pragma unroll
        for (int c = 0; c < 8; c++) {
            float t = fmaxf(vv[c] * __ldg(sc + c8 + c) + __ldg(sh + c8 + c), 0.0f);
            hh[c] = __float2half_rn(t);
        }
        *reinterpret_cast<uint4*>(as + m * K + c8) = *reinterpret_cast<uint4*>(hh);
    }
}

// ---------------- partition rows by seg0 match (matched first) ----------------
__global__ void partition_kernel(int M1) {
    int i = blockIdx.x * blockDim.x + threadIdx.x;
    if (i >= M1) return;
    if (g_idx0[i] >= 0) {
        int p = atomicAdd(&g_cnt[0], 1);
        g_perm[p] = i;
    } else {
        int p = atomicAdd(&g_cnt[1], 1);
        g_perm[M1 - 1 - p] = i;
    }
}

// ---------------- mma helpers ----------------
__device__ __forceinline__ uint32_t smem_u32(const void* p) {
    uint32_t a;
    asm("{ .reg .u64 t; cvta.to.shared.u64 t, %1; cvt.u32.u64 %0, t; }" : "=r"(a) : "l"(p));
    return a;
}
__device__ __forceinline__ void mma_fp16(float* d, const uint32_t* a, const uint32_t* b) {
    asm volatile(
        "mma.sync.aligned.m16n8k16.row.col.f32.f16.f16.f32 "
        "{%0,%1,%2,%3}, {%4,%5,%6,%7}, {%8,%9}, {%0,%1,%2,%3};"
        : "+f"(d[0]), "+f"(d[1]), "+f"(d[2]), "+f"(d[3])
        : "r"(a[0]), "r"(a[1]), "r"(a[2]), "r"(a[3]), "r"(b[0]), "r"(b[1]));
}
__device__ __forceinline__ void ldsm_x4(uint32_t* r, uint32_t addr) {
    asm volatile("ldmatrix.sync.aligned.m8n8.x4.shared.b16 {%0,%1,%2,%3}, [%4];"
                 : "=r"(r[0]), "=r"(r[1]), "=r"(r[2]), "=r"(r[3]) : "r"(addr));
}
__device__ __forceinline__ void cp_async16(uint32_t dst, const void* src) {
    asm volatile("cp.async.cg.shared.global [%0], [%1], 16;" :: "r"(dst), "l"(src) : "memory");
}
__device__ __forceinline__ void cp_async16z(uint32_t dst, const void* src, uint32_t srcsz) {
    asm volatile("cp.async.cg.shared.global [%0], [%1], 16, %2;"
                 :: "r"(dst), "l"(src), "r"(srcsz) : "memory");
}
__device__ __forceinline__ void cp_commit() {
    asm volatile("cp.async.commit_group;" ::: "memory");
}
__device__ __forceinline__ void cp_wait_all() {
    asm volatile("cp.async.wait_group 0;" ::: "memory");
}

// ---------------- fp16 2-term tensor GEMM ----------------
// D = A * (Wh + Wl): A single fp16 plane, W split fp16 hi/lo (products exact, f32 accum).
// CTA 128x128, 8 warps (warp tile 64x32), K-chunk 32, double buffered, pure cp.async.
// MODE 1: A rows contiguous in plane. MODE 2: rows via g_perm (matched-seg0 first);
//   blocks with bm >= g_cnt[0] skip the first 8 K-chunks (seg0 all-zero rows).
template<int MODE>
__global__ void __launch_bounds__(256, 2)
mma_gemm(int K, int woff, size_t Wstr,
         float* __restrict__ Cbase, size_t Cstr,
         int3 Ms, int N,
         float* __restrict__ stbase) {
    constexpr int RS = 20;               // smem row stride in u32 (80B)
    int s = blockIdx.z;
    int M = (MODE == 2) ? Ms.y : ((s == 0) ? Ms.x : (s == 1) ? Ms.y : Ms.z);
    int bm = blockIdx.y * 128;
    if (bm >= M) return;
    int bn = blockIdx.x * 128;

    const __half* Ap = g_a16 + (size_t)s * MAXM * K;
    const __half* Wh = g_wh + woff + (size_t)s * Wstr;
    const __half* Wl = g_wl + woff + (size_t)s * Wstr;
    float* Cp = Cbase + (size_t)s * Cstr;
    float* st = stbase + (size_t)s * 1536;

    __shared__ uint32_t sA[2][128 * RS];
    __shared__ uint32_t sBh[2][128 * RS], sBl[2][128 * RS];
    __shared__ float s_sum[128], s_sq[128];

    int tid = threadIdx.x;
    int lane = tid & 31, warp = tid >> 5;
    int warpM = warp & 1, warpN = warp >> 1;

    for (int c = tid; c < 128; c += 256) { s_sum[c] = 0.0f; s_sq[c] = 0.0f; }

    uint32_t baseA = smem_u32(sA[0]);
    uint32_t baseBh = smem_u32(sBh[0]), baseBl = smem_u32(sBl[0]);

    float acc[4][4][4];
    #pragma unroll
    for (int f = 0; f < 4; f++)
        #pragma unroll
        for (int g = 0; g < 4; g++)
            #pragma unroll
            for (int r = 0; r < 4; r++) acc[f][g][r] = 0.0f;

    int a_row = lane & 15;
    int a_koff = (lane & 16) ? 16 : 0;
    int b4_row = (lane & 7) + ((lane & 16) ? 8 : 0);
    int b4_koff = (lane & 8) ? 16 : 0;

    auto issueAB = [&](int t, int buf) {
        int tk = t * 32;
        uint32_t a0 = baseA + (uint32_t)buf * (128 * RS * 4);
        uint32_t bh0 = baseBh + (uint32_t)buf * (128 * RS * 4);
        uint32_t bl0 = baseBl + (uint32_t)buf * (128 * RS * 4);
        #pragma unroll
        for (int i = 0; i < 2; i++) {
            int v = tid + i * 256;
            int r = v >> 2, q = v & 3;
            int gk = tk + q * 8;
            uint32_t dst = (uint32_t)(r * 80 + q * 16);
            // A row r
            if (MODE == 1) {
                int gm = bm + r;
                cp_async16(a0 + dst, Ap + (size_t)gm * K + gk);
            } else {
                int gm = bm + r;
                int orig = (gm < M) ? g_perm[gm] : -1;
                int seg = gk >> 8, off = gk & 255;
                int j = -1;
                if (orig >= 0) {
                    if (seg == 0) j = g_idx0[orig];
                    else if (seg == 1) j = orig;
                    else j = g_idx2[orig];
                }
                uint32_t ok = (j >= 0) ? 16u : 0u;
                size_t srow = (size_t)seg * MAXM + (j >= 0 ? j : 0);
                cp_async16z(a0 + dst, g_a16 + srow * 256 + off, ok);
            }
            // B row r (both planes)
            int gn = bn + r;
            cp_async16(bh0 + dst, Wh + (size_t)gn * K + gk);
            cp_async16(bl0 + dst, Wl + (size_t)gn * K + gk);
        }
        cp_commit();
    };

    int nch = K / 32;
    int tstart = 0;
    if (MODE == 2 && bm >= g_cnt[0]) tstart = 8;   // all seg0 rows unmatched -> skip K[0:256)
    issueAB(tstart, tstart & 1);

    for (int t = tstart; t < nch; t++) {
        cp_wait_all();
        __syncthreads();
        if (t + 1 < nch) issueAB(t + 1, (t + 1) & 1);
        int buf = t & 1;
        uint32_t off0 = (uint32_t)buf * (128 * RS * 4);

        #pragma unroll
        for (int kk = 0; kk < 32; kk += 16) {
            uint32_t bh[4][2], bl[4][2];
            #pragma unroll
            for (int gp = 0; gp < 2; gp++) {
                int n0 = warpN * 32 + gp * 16;
                uint32_t off = off0 + (uint32_t)((n0 + b4_row) * 80 + kk * 2 + b4_koff);
                uint32_t tm[4];
                ldsm_x4(tm, baseBh + off);
                bh[2 * gp][0] = tm[0]; bh[2 * gp][1] = tm[1];
                bh[2 * gp + 1][0] = tm[2]; bh[2 * gp + 1][1] = tm[3];
                ldsm_x4(tm, baseBl + off);
                bl[2 * gp][0] = tm[0]; bl[2 * gp][1] = tm[1];
                bl[2 * gp + 1][0] = tm[2]; bl[2 * gp + 1][1] = tm[3];
            }
            #pragma unroll
            for (int f = 0; f < 4; f++) {
                int m0 = warpM * 64 + f * 16;
                uint32_t off = off0 + (uint32_t)((m0 + a_row) * 80 + kk * 2 + a_koff);
                uint32_t av[4];
                ldsm_x4(av, baseA + off);
                #pragma unroll
                for (int g = 0; g < 4; g++) {
                    mma_fp16(acc[f][g], av, bh[g]);
                    mma_fp16(acc[f][g], av, bl[g]);
                }
            }
        }
    }

    // ---- epilogue: store C + fused column stats ----
    float csum[4][2], csq[4][2];
    #pragma unroll
    for (int g = 0; g < 4; g++) { csum[g][0] = csum[g][1] = 0.f; csq[g][0] = csq[g][1] = 0.f; }

    int qr = lane >> 2, qc = lane & 3;
    #pragma unroll
    for (int f = 0; f < 4; f++) {
        int r0 = bm + warpM * 64 + f * 16 + qr;
        int r1 = r0 + 8;
        int o0 = (r0 < M) ? ((MODE == 2) ? g_perm[r0] : r0) : -1;
        int o1 = (r1 < M) ? ((MODE == 2) ? g_perm[r1] : r1) : -1;
        #pragma unroll
        for (int g = 0; g < 4; g++) {
            int c0 = bn + warpN * 32 + g * 8 + 2 * qc;
            if (o0 >= 0) {
                *reinterpret_cast<float2*>(Cp + (size_t)o0 * N + c0) =
                    make_float2(acc[f][g][0], acc[f][g][1]);
                csum[g][0] += acc[f][g][0]; csq[g][0] += acc[f][g][0] * acc[f][g][0];
                csum[g][1] += acc[f][g][1]; csq[g][1] += acc[f][g][1] * acc[f][g][1];
            }
            if (o1 >= 0) {
                *reinterpret_cast<float2*>(Cp + (size_t)o1 * N + c0) =
                    make_float2(acc[f][g][2], acc[f][g][3]);
                csum[g][0] += acc[f][g][2]; csq[g][0] += acc[f][g][2] * acc[f][g][2];
                csum[g][1] += acc[f][g][3]; csq[g][1] += acc[f][g][3] * acc[f][g][3];
            }
        }
    }
    __syncthreads();
    #pragma unroll
    for (int g = 0; g < 4; g++) {
        int cl = warpN * 32 + g * 8 + 2 * qc;
        atomicAdd(&s_sum[cl], csum[g][0]);     atomicAdd(&s_sq[cl], csq[g][0]);
        atomicAdd(&s_sum[cl + 1], csum[g][1]); atomicAdd(&s_sq[cl + 1], csq[g][1]);
    }
    __syncthreads();
    for (int c = tid; c < 128; c += 256) {
        atomicAdd(&st[bn + c],     s_sum[c]);
        atomicAdd(&st[N + bn + c], s_sq[c]);
    }
}

// ---------------- BN + ReLU (final output only) ----------------
__global__ void bnrelu_kernel(const float* __restrict__ Y, float* __restrict__ Z,
                              int M, int C, const float* __restrict__ st,
                              const float* __restrict__ G, const float* __restrict__ B) {
    size_t total = (size_t)M * C;
    size_t stride = (size_t)gridDim.x * blockDim.x;
    float invM = 1.0f / (float)M;
    for (size_t i = (size_t)blockIdx.x * blockDim.x + threadIdx.x; i < total; i += stride) {
        int c = (int)(i % C);
        float m = st[c] * invM;
        float v = st[C + c] * invM - m * m;
        float sc = rsqrtf(fmaxf(v, 0.0f) + 1e-5f);
        float z = (Y[i] - m) * sc * G[c] + B[c];
        Z[i] = fmaxf(z, 0.0f);
    }
}

// ---------------- alignment (matches jitted reference bit-exactly) ----------------
__device__ __forceinline__ int lower_bound_i32(const int* __restrict__ a, int n, int key) {
    int lo = 0, hi = n;
    while (lo < hi) {
        int mid = (lo + hi) >> 1;
        if (a[mid] < key) lo = mid + 1; else hi = mid;
    }
    return lo;
}

__global__ void align_kernel(const int* __restrict__ uc1, int M1,
                             const int* __restrict__ keys0, int M0,
                             const int* __restrict__ keys2, int M2) {
    int i = blockIdx.x * blockDim.x + threadIdx.x;
    if (i >= M1) return;
    int b  = uc1[4 * i + 0];
    int cx = uc1[4 * i + 1];
    int cy = uc1[4 * i + 2];
    int cz = uc1[4 * i + 3];
    float rx = __fadd_rn(__fmul_rn(__fadd_rn((float)cx, 0.5f), 0.2f), -50.0f);
    float ry = __fadd_rn(__fmul_rn(__fadd_rn((float)cy, 0.5f), 0.2f), -50.0f);
    float rz = __fadd_rn(__fmul_rn(__fadd_rn((float)cz, 0.5f), 0.2f), -3.0f);
    float dx = __fsub_rn(rx, -50.0f);
    float dy = __fsub_rn(ry, -50.0f);
    float dz = __fsub_rn(rz, -3.0f);
    {
        int ix = (int)floorf(__fmul_rn(dx, 10.0f)); ix = min(max(ix, 0), 999);
        int iy = (int)floorf(__fmul_rn(dy, 10.0f)); iy = min(max(iy, 0), 999);
        int iz = (int)floorf(__fmul_rn(dz, 10.0f)); iz = min(max(iz, 0), 59);
        int k = b * 1000000000 + ix * 1000000 + iy * 1000 + iz;
        int lo = lower_bound_i32(keys0, M0, k);
        int idx = min(lo, M0 - 1); if (idx < 0) idx = 0;
        g_idx0[i] = (keys0[idx] == k) ? idx : -1;
    }
    {
        int ix = (int)floorf(__fmul_rn(dx, 2.5f)); ix = min(max(ix, 0), 249);
        int iy = (int)floorf(__fmul_rn(dy, 2.5f)); iy = min(max(iy, 0), 249);
        int iz = (int)floorf(__fmul_rn(dz, 2.5f)); iz = min(max(iz, 0), 14);
        int k = b * 1000000000 + ix * 1000000 + iy * 1000 + iz;
        int lo = lower_bound_i32(keys2, M2, k);
        int idx = min(lo, M2 - 1); if (idx < 0) idx = 0;
        g_idx2[i] = (keys2[idx] == k) ? idx : -1;
    }
}

// ---------------- host orchestration ----------------
extern "C" void kernel_launch(void* const* d_in, const int* in_sizes, int n_in,
                              void* d_out, int out_size) {
    (void)n_in; (void)out_size;
    const float* points = (const float*)d_in[0];
    const float* W1 = (const float*)d_in[1];
    const float* G1 = (const float*)d_in[2];
    const float* B1 = (const float*)d_in[3];
    const float* W2 = (const float*)d_in[4];
    const float* G2 = (const float*)d_in[5];
    const float* B2 = (const float*)d_in[6];
    const float* W3 = (const float*)d_in[7];
    const float* G3 = (const float*)d_in[8];
    const float* B3 = (const float*)d_in[9];
    const float* Wf = (const float*)d_in[10];
    const float* Gf = (const float*)d_in[11];
    const float* Bf = (const float*)d_in[12];
    const int* inv0 = (const int*)d_in[13];
    const int* inv1 = (const int*)d_in[14];
    const int* inv2 = (const int*)d_in[15];
    const int* keys0 = (const int*)d_in[16];
    const int* keys2 = (const int*)d_in[17];
    const int* uc1   = (const int*)d_in[18];

    int N  = in_sizes[0] / 4;
    int M0 = in_sizes[16];
    int M2 = in_sizes[17];
    int M1 = in_sizes[18] / 4;
    int maxM = M0 > M1 ? M0 : M1; if (M2 > maxM) maxM = M2;
    int3 Ms3 = make_int3(M0, M1, M2);

    float *t64, *t128, *feat, *y, *stats, *bnp;
    cudaGetSymbolAddress((void**)&t64,  g_t64);
    cudaGetSymbolAddress((void**)&t128, g_t128);
    cudaGetSymbolAddress((void**)&feat, g_feat);
    cudaGetSymbolAddress((void**)&y,    g_y);
    cudaGetSymbolAddress((void**)&stats, g_stats);
    cudaGetSymbolAddress((void**)&bnp,   g_bnp);

    zero_kernel<<<2048, 256>>>();
    wconv_kernel<<<(WTOT + 255) / 256, 256>>>(W2, W3, Wf);
    scatter_kernel<<<(N + 255) / 256, 256>>>(points, inv0, inv1, inv2, N);
    align_kernel<<<(M1 + 255) / 256, 256>>>(uc1, M1, keys0, M0, keys2, M2);
    partition_kernel<<<(M1 + 255) / 256, 256>>>(M1);

    // Layer 1 fused (mean + K=4 GEMM + stats)
    l1_kernel<<<dim3((maxM + 511) / 512, 3), 256>>>(W1, Ms3);
    finalize_kernel<<<dim3(1, 3), 64>>>(stats, bnp, G1, B1, 64, Ms3);
    xform_kernel<<<dim3(512, 3), 256>>>(t64, 64, Ms3, bnp);

    int gy = (maxM + 127) / 128;

    // Layer 2: [M,64] -> [M,128]
    mma_gemm<1><<<dim3(1, gy, 3), 256>>>(64, WOFF2, 128 * 64,
                                         t128, (size_t)MAXM * 128, Ms3, 128,
                                         stats + 4608);
    finalize_kernel<<<dim3(1, 3), 128>>>(stats + 4608, bnp + 4608, G2, B2, 128, Ms3);
    xform_kernel<<<dim3(512, 3), 256>>>(t128, 128, Ms3, bnp + 4608);

    // Layer 3: [M,128] -> [M,256]
    mma_gemm<1><<<dim3(2, gy, 3), 256>>>(128, WOFF3, 256 * 128,
                                         feat, (size_t)MAXM * 256, Ms3, 256,
                                         stats + 9216);
    finalize_kernel<<<dim3(1, 3), 256>>>(stats + 9216, bnp + 9216, G3, B3, 256, Ms3);
    xform_kernel<<<dim3(512, 3), 256>>>(feat, 256, Ms3, bnp + 9216);

    // Final: gather [M1,768] -> [M1,256], seg0-skip for unmatched rows
    mma_gemm<2><<<dim3(2, (M1 + 127) / 128, 1), 256>>>(768, WOFFF, 0,
                                                       y, 0, Ms3, 256,
                                                       stats + 13824);

    bnrelu_kernel<<<4096, 256>>>(y, (float*)d_out, M1, 256, stats + 13824, Gf, Bf);
}

// round 17
// speedup vs baseline: 1.2172x; 1.0037x over previous
#include <cuda_runtime.h>
#include <cuda_fp16.h>
#include <math.h>
#include <stdint.h>

#define MAXM 200000

// weight plane offsets (elements)
#define WOFF2 0
#define WOFF3 24576          // 3*128*64
#define WOFFF 122880         // WOFF3 + 3*256*128
#define WTOT  319488         // WOFFF + 256*768

// ---------------- static device scratch ----------------
__device__ float g_acc[(size_t)3 * MAXM * 8];     // padded: [x,y,z,i,cnt,0,0,0] per voxel
__device__ float g_t64[(size_t)3 * MAXM * 64];    // layer1 out, pre-BN fp32
__device__ float g_t128[(size_t)3 * MAXM * 128];  // layer2 out, pre-BN fp32
__device__ float g_feat[(size_t)3 * MAXM * 256];  // layer3 out, pre-BN fp32
__device__ float g_y[(size_t)MAXM * 256];         // final pre-BN
__device__ float g_stats[10 * 1536];
__device__ float g_bnp[10 * 1536];
__device__ int   g_idx0[MAXM];
__device__ int   g_idx2[MAXM];
__device__ int   g_perm[MAXM];                    // matched-seg0 rows first
__device__ int   g_cnt[2];
__device__ __half g_wh[WTOT];                     // weight hi plane (fp16)
__device__ __half g_wl[WTOT];                     // weight lo plane (fp16 residual)
__device__ __half g_a16[(size_t)3 * MAXM * 256];  // activation fp16 plane (post-BN+ReLU)

// ---------------- zero scratch ----------------
__global__ void zero_kernel() {
    const size_t n1 = (size_t)3 * MAXM * 8;
    const size_t total = n1 + 10 * 1536;
    const size_t stride = (size_t)gridDim.x * blockDim.x;
    size_t i0 = (size_t)blockIdx.x * blockDim.x + threadIdx.x;
    if (i0 == 0) { g_cnt[0] = 0; g_cnt[1] = 0; }
    for (size_t i = i0; i < total; i += stride) {
        if (i < n1) g_acc[i] = 0.0f;
        else        g_stats[i - n1] = 0.0f;
    }
}

// ---------------- weight pre-conversion to split fp16 ----------------
__global__ void wconv_kernel(const float* __restrict__ W2, const float* __restrict__ W3,
                             const float* __restrict__ Wf) {
    int i = blockIdx.x * blockDim.x + threadIdx.x;
    if (i >= WTOT) return;
    float v;
    if (i < WOFF3) v = W2[i];
    else if (i < WOFFF) v = W3[i - WOFF3];
    else v = Wf[i - WOFFF];
    __half h = __float2half_rn(v);
    g_wh[i] = h;
    g_wl[i] = __float2half_rn(v - __half2float(h));
}

// ---------------- scatter: vectorized reductions ----------------
__device__ __forceinline__ void red4(float* p, float4 v) {
    asm volatile("red.global.add.v4.f32 [%0], {%1, %2, %3, %4};"
                 :: "l"(p), "f"(v.x), "f"(v.y), "f"(v.z), "f"(v.w) : "memory");
}
__device__ __forceinline__ void red1(float* p, float v) {
    asm volatile("red.global.add.f32 [%0], %1;" :: "l"(p), "f"(v) : "memory");
}

__global__ void scatter_kernel(const float* __restrict__ pts,
                               const int* __restrict__ inv0,
                               const int* __restrict__ inv1,
                               const int* __restrict__ inv2, int N) {
    int i = blockIdx.x * blockDim.x + threadIdx.x;
    if (i >= N) return;
    float4 p = reinterpret_cast<const float4*>(pts)[i];
    int m0 = inv0[i], m1 = inv1[i], m2 = inv2[i];
    float* a0 = g_acc + (size_t)m0 * 8;
    float* a1 = g_acc + (size_t)MAXM * 8 + (size_t)m1 * 8;
    float* a2 = g_acc + (size_t)2 * MAXM * 8 + (size_t)m2 * 8;
    red4(a0, p); red1(a0 + 4, 1.0f);
    red4(a1, p); red1(a1 + 4, 1.0f);
    red4(a2, p); red1(a2 + 4, 1.0f);
}

// ---------------- fused mean + layer1 (K=4 -> 64) + column stats ----------------
__global__ void l1_kernel(const float* __restrict__ W1, int3 Ms) {
    int s = blockIdx.y;
    int M = (s == 0) ? Ms.x : (s == 1) ? Ms.y : Ms.z;
    __shared__ float Wsm[256];
    __shared__ float s_sum[64], s_sq[64];
    int tid = threadIdx.x;
    Wsm[tid] = W1[s * 256 + tid];
    if (tid < 64) { s_sum[tid] = 0.0f; s_sq[tid] = 0.0f; }
    __syncthreads();
    int lane = tid & 31, w = tid >> 5;
    int c0 = lane * 2;
    float w00 = Wsm[c0 * 4 + 0], w01 = Wsm[c0 * 4 + 1], w02 = Wsm[c0 * 4 + 2], w03 = Wsm[c0 * 4 + 3];
    float w10 = Wsm[c0 * 4 + 4], w11 = Wsm[c0 * 4 + 5], w12 = Wsm[c0 * 4 + 6], w13 = Wsm[c0 * 4 + 7];
    const float* acc = g_acc + (size_t)s * MAXM * 8;
    float* out = g_t64 + (size_t)s * MAXM * 64;
    float sum0 = 0, sq0 = 0, sum1 = 0, sq1 = 0;
    int base = blockIdx.x * 512;
    if (base >= M) return;
    int lim = min(base + 512, M);
    for (int r = base + w; r < lim; r += 8) {
        const float* a = acc + (size_t)r * 8;
        float4 xs = *reinterpret_cast<const float4*>(a);
        float cnt = fmaxf(__ldg(a + 4), 1.0f);
        float inv = 1.0f / cnt;
        float x0 = xs.x * inv, x1 = xs.y * inv, x2 = xs.z * inv, x3 = xs.w * inv;
        float o0 = x0 * w00 + x1 * w01 + x2 * w02 + x3 * w03;
        float o1 = x0 * w10 + x1 * w11 + x2 * w12 + x3 * w13;
        *reinterpret_cast<float2*>(out + (size_t)r * 64 + c0) = make_float2(o0, o1);
        sum0 += o0; sq0 += o0 * o0; sum1 += o1; sq1 += o1 * o1;
    }
    atomicAdd(&s_sum[c0], sum0);     atomicAdd(&s_sq[c0], sq0);
    atomicAdd(&s_sum[c0 + 1], sum1); atomicAdd(&s_sq[c0 + 1], sq1);
    __syncthreads();
    if (tid < 64) {
        atomicAdd(&g_stats[s * 1536 + tid], s_sum[tid]);
        atomicAdd(&g_stats[s * 1536 + 64 + tid], s_sq[tid]);
    }
}

// NOTE: l1 uses x/cnt as a*inv (reciprocal); reference divides. 1-ulp difference on the
// mean feeds a smooth MLP (no floor boundaries), so impact is ~1e-7 — far under budget.

// ---------------- finalize: raw sum/sumsq -> (scale, shift) ----------------
__global__ void finalize_kernel(const float* __restrict__ st, float* __restrict__ bnp,
                                const float* __restrict__ G, const float* __restrict__ Bb,
                                int C, int3 Ms) {
    int s = blockIdx.y;
    int c = blockIdx.x * blockDim.x + threadIdx.x;
    if (c >= C) return;
    float M = (float)((s == 0) ? Ms.x : (s == 1) ? Ms.y : Ms.z);
    const float* stb = st + (size_t)s * 1536;
    float m = stb[c] / M;
    float v = stb[C + c] / M - m * m;
    float rs = rsqrtf(fmaxf(v, 0.0f) + 1e-5f);
    float sc = rs * G[s * C + c];
    float sh = Bb[s * C + c] - m * sc;
    bnp[(size_t)s * 1536 + c] = sc;
    bnp[(size_t)s * 1536 + C + c] = sh;
}

// ---------------- xform: pre-BN fp32 -> post-BN+ReLU fp16 plane ----------------
__global__ void xform_kernel(const float* __restrict__ X, int K, int3 Ms,
                             const float* __restrict__ bnp) {
    int s = blockIdx.y;
    int M = (s == 0) ? Ms.x : (s == 1) ? Ms.y : Ms.z;
    const float* Xs = X + (size_t)s * MAXM * K;
    const float* sc = bnp + (size_t)s * 1536;
    const float* sh = sc + K;
    __half* as = g_a16 + (size_t)s * MAXM * K;
    int kc = K >> 3;
    size_t total = (size_t)M * kc;
    size_t stride = (size_t)gridDim.x * blockDim.x;
    for (size_t idx = (size_t)blockIdx.x * blockDim.x + threadIdx.x; idx < total; idx += stride) {
        size_t m = idx / kc;
        int c8 = (int)(idx - m * kc) * 8;
        const float* p = Xs + m * K + c8;
        float4 v0 = *reinterpret_cast<const float4*>(p);
        float4 v1 = *reinterpret_cast<const float4*>(p + 4);
        float vv[8] = {v0.x, v0.y, v0.z, v0.w, v1.x, v1.y, v1.z, v1.w};
        __half hh[8];
        #pragma unroll
        for (int c = 0; c < 8; c++) {
            float t = fmaxf(vv[c] * __ldg(sc + c8 + c) + __ldg(sh + c8 + c), 0.0f);
            hh[c] = __float2half_rn(t);
        }
        *reinterpret_cast<uint4*>(as + m * K + c8) = *reinterpret_cast<uint4*>(hh);
    }
}

// ---------------- mma helpers ----------------
__device__ __forceinline__ uint32_t smem_u32(const void* p) {
    uint32_t a;
    asm("{ .reg .u64 t; cvta.to.shared.u64 t, %1; cvt.u32.u64 %0, t; }" : "=r"(a) : "l"(p));
    return a;
}
__device__ __forceinline__ void mma_fp16(float* d, const uint32_t* a, const uint32_t* b) {
    asm volatile(
        "mma.sync.aligned.m16n8k16.row.col.f32.f16.f16.f32 "
        "{%0,%1,%2,%3}, {%4,%5,%6,%7}, {%8,%9}, {%0,%1,%2,%3};"
        : "+f"(d[0]), "+f"(d[1]), "+f"(d[2]), "+f"(d[3])
        : "r"(a[0]), "r"(a[1]), "r"(a[2]), "r"(a[3]), "r"(b[0]), "r"(b[1]));
}
__device__ __forceinline__ void ldsm_x4(uint32_t* r, uint32_t addr) {
    asm volatile("ldmatrix.sync.aligned.m8n8.x4.shared.b16 {%0,%1,%2,%3}, [%4];"
                 : "=r"(r[0]), "=r"(r[1]), "=r"(r[2]), "=r"(r[3]) : "r"(addr));
}
__device__ __forceinline__ void cp_async16(uint32_t dst, const void* src) {
    asm volatile("cp.async.cg.shared.global [%0], [%1], 16;" :: "r"(dst), "l"(src) : "memory");
}
__device__ __forceinline__ void cp_async16z(uint32_t dst, const void* src, uint32_t srcsz) {
    asm volatile("cp.async.cg.shared.global [%0], [%1], 16, %2;"
                 :: "r"(dst), "l"(src), "r"(srcsz) : "memory");
}
__device__ __forceinline__ void cp_commit() {
    asm volatile("cp.async.commit_group;" ::: "memory");
}
__device__ __forceinline__ void cp_wait_all() {
    asm volatile("cp.async.wait_group 0;" ::: "memory");
}

// ---------------- fp16 2-term tensor GEMM ----------------
// D = A * (Wh + Wl): A single fp16 plane, W split fp16 hi/lo (products exact, f32 accum).
// CTA 128x128, 8 warps (warp tile 64x32), K-chunk 32, double buffered, pure cp.async.
// MODE 1: A rows contiguous in plane. MODE 2: rows via g_perm (matched-seg0 first);
//   blocks with bm >= g_cnt[0] skip the first 8 K-chunks (seg0 all-zero rows).
template<int MODE>
__global__ void __launch_bounds__(256, 2)
mma_gemm(int K, int woff, size_t Wstr,
         float* __restrict__ Cbase, size_t Cstr,
         int3 Ms, int N,
         float* __restrict__ stbase) {
    constexpr int RS = 20;               // smem row stride in u32 (80B)
    int s = blockIdx.z;
    int M = (MODE == 2) ? Ms.y : ((s == 0) ? Ms.x : (s == 1) ? Ms.y : Ms.z);
    int bm = blockIdx.y * 128;
    if (bm >= M) return;
    int bn = blockIdx.x * 128;

    const __half* Ap = g_a16 + (size_t)s * MAXM * K;
    const __half* Wh = g_wh + woff + (size_t)s * Wstr;
    const __half* Wl = g_wl + woff + (size_t)s * Wstr;
    float* Cp = Cbase + (size_t)s * Cstr;
    float* st = stbase + (size_t)s * 1536;

    __shared__ uint32_t sA[2][128 * RS];
    __shared__ uint32_t sBh[2][128 * RS], sBl[2][128 * RS];
    __shared__ float s_sum[128], s_sq[128];

    int tid = threadIdx.x;
    int lane = tid & 31, warp = tid >> 5;
    int warpM = warp & 1, warpN = warp >> 1;

    for (int c = tid; c < 128; c += 256) { s_sum[c] = 0.0f; s_sq[c] = 0.0f; }

    uint32_t baseA = smem_u32(sA[0]);
    uint32_t baseBh = smem_u32(sBh[0]), baseBl = smem_u32(sBl[0]);

    float acc[4][4][4];
    #pragma unroll
    for (int f = 0; f < 4; f++)
        #pragma unroll
        for (int g = 0; g < 4; g++)
            #pragma unroll
            for (int r = 0; r < 4; r++) acc[f][g][r] = 0.0f;

    int a_row = lane & 15;
    int a_koff = (lane & 16) ? 16 : 0;
    int b4_row = (lane & 7) + ((lane & 16) ? 8 : 0);
    int b4_koff = (lane & 8) ? 16 : 0;

    auto issueAB = [&](int t, int buf) {
        int tk = t * 32;
        uint32_t a0 = baseA + (uint32_t)buf * (128 * RS * 4);
        uint32_t bh0 = baseBh + (uint32_t)buf * (128 * RS * 4);
        uint32_t bl0 = baseBl + (uint32_t)buf * (128 * RS * 4);
        #pragma unroll
        for (int i = 0; i < 2; i++) {
            int v = tid + i * 256;
            int r = v >> 2, q = v & 3;
            int gk = tk + q * 8;
            uint32_t dst = (uint32_t)(r * 80 + q * 16);
            // A row r
            if (MODE == 1) {
                int gm = bm + r;
                cp_async16(a0 + dst, Ap + (size_t)gm * K + gk);
            } else {
                int gm = bm + r;
                int orig = (gm < M) ? g_perm[gm] : -1;
                int seg = gk >> 8, off = gk & 255;
                int j = -1;
                if (orig >= 0) {
                    if (seg == 0) j = g_idx0[orig];
                    else if (seg == 1) j = orig;
                    else j = g_idx2[orig];
                }
                uint32_t ok = (j >= 0) ? 16u : 0u;
                size_t srow = (size_t)seg * MAXM + (j >= 0 ? j : 0);
                cp_async16z(a0 + dst, g_a16 + srow * 256 + off, ok);
            }
            // B row r (both planes)
            int gn = bn + r;
            cp_async16(bh0 + dst, Wh + (size_t)gn * K + gk);
            cp_async16(bl0 + dst, Wl + (size_t)gn * K + gk);
        }
        cp_commit();
    };

    int nch = K / 32;
    int tstart = 0;
    if (MODE == 2 && bm >= g_cnt[0]) tstart = 8;   // all seg0 rows unmatched -> skip K[0:256)
    issueAB(tstart, tstart & 1);

    for (int t = tstart; t < nch; t++) {
        cp_wait_all();
        __syncthreads();
        if (t + 1 < nch) issueAB(t + 1, (t + 1) & 1);
        int buf = t & 1;
        uint32_t off0 = (uint32_t)buf * (128 * RS * 4);

        #pragma unroll
        for (int kk = 0; kk < 32; kk += 16) {
            uint32_t bh[4][2], bl[4][2];
            #pragma unroll
            for (int gp = 0; gp < 2; gp++) {
                int n0 = warpN * 32 + gp * 16;
                uint32_t off = off0 + (uint32_t)((n0 + b4_row) * 80 + kk * 2 + b4_koff);
                uint32_t tm[4];
                ldsm_x4(tm, baseBh + off);
                bh[2 * gp][0] = tm[0]; bh[2 * gp][1] = tm[1];
                bh[2 * gp + 1][0] = tm[2]; bh[2 * gp + 1][1] = tm[3];
                ldsm_x4(tm, baseBl + off);
                bl[2 * gp][0] = tm[0]; bl[2 * gp][1] = tm[1];
                bl[2 * gp + 1][0] = tm[2]; bl[2 * gp + 1][1] = tm[3];
            }
            #pragma unroll
            for (int f = 0; f < 4; f++) {
                int m0 = warpM * 64 + f * 16;
                uint32_t off = off0 + (uint32_t)((m0 + a_row) * 80 + kk * 2 + a_koff);
                uint32_t av[4];
                ldsm_x4(av, baseA + off);
                #pragma unroll
                for (int g = 0; g < 4; g++) {
                    mma_fp16(acc[f][g], av, bh[g]);
                    mma_fp16(acc[f][g], av, bl[g]);
                }
            }
        }
    }

    // ---- epilogue: store C + fused column stats ----
    float csum[4][2], csq[4][2];
    #pragma unroll
    for (int g = 0; g < 4; g++) { csum[g][0] = csum[g][1] = 0.f; csq[g][0] = csq[g][1] = 0.f; }

    int qr = lane >> 2, qc = lane & 3;
    #pragma unroll
    for (int f = 0; f < 4; f++) {
        int r0 = bm + warpM * 64 + f * 16 + qr;
        int r1 = r0 + 8;
        int o0 = (r0 < M) ? ((MODE == 2) ? g_perm[r0] : r0) : -1;
        int o1 = (r1 < M) ? ((MODE == 2) ? g_perm[r1] : r1) : -1;
        #pragma unroll
        for (int g = 0; g < 4; g++) {
            int c0 = bn + warpN * 32 + g * 8 + 2 * qc;
            if (o0 >= 0) {
                *reinterpret_cast<float2*>(Cp + (size_t)o0 * N + c0) =
                    make_float2(acc[f][g][0], acc[f][g][1]);
                csum[g][0] += acc[f][g][0]; csq[g][0] += acc[f][g][0] * acc[f][g][0];
                csum[g][1] += acc[f][g][1]; csq[g][1] += acc[f][g][1] * acc[f][g][1];
            }
            if (o1 >= 0) {
                *reinterpret_cast<float2*>(Cp + (size_t)o1 * N + c0) =
                    make_float2(acc[f][g][2], acc[f][g][3]);
                csum[g][0] += acc[f][g][2]; csq[g][0] += acc[f][g][2] * acc[f][g][2];
                csum[g][1] += acc[f][g][3]; csq[g][1] += acc[f][g][3] * acc[f][g][3];
            }
        }
    }
    __syncthreads();
    #pragma unroll
    for (int g = 0; g < 4; g++) {
        int cl = warpN * 32 + g * 8 + 2 * qc;
        atomicAdd(&s_sum[cl], csum[g][0]);     atomicAdd(&s_sq[cl], csq[g][0]);
        atomicAdd(&s_sum[cl + 1], csum[g][1]); atomicAdd(&s_sq[cl + 1], csq[g][1]);
    }
    __syncthreads();
    for (int c = tid; c < 128; c += 256) {
        atomicAdd(&st[bn + c],     s_sum[c]);
        atomicAdd(&st[N + bn + c], s_sq[c]);
    }
}

// ---------------- BN + ReLU (final output only) ----------------
__global__ void bnrelu_kernel(const float* __restrict__ Y, float* __restrict__ Z,
                              int M, int C, const float* __restrict__ st,
                              const float* __restrict__ G, const float* __restrict__ B) {
    size_t total = (size_t)M * C;
    size_t stride = (size_t)gridDim.x * blockDim.x;
    float invM = 1.0f / (float)M;
    for (size_t i = (size_t)blockIdx.x * blockDim.x + threadIdx.x; i < total; i += stride) {
        int c = (int)(i % C);
        float m = st[c] * invM;
        float v = st[C + c] * invM - m * m;
        float sc = rsqrtf(fmaxf(v, 0.0f) + 1e-5f);
        float z = (Y[i] - m) * sc * G[c] + B[c];
        Z[i] = fmaxf(z, 0.0f);
    }
}

// ---------------- alignment + partition (matches jitted reference bit-exactly) ----------------
__device__ __forceinline__ int lower_bound_i32(const int* __restrict__ a, int n, int key) {
    int lo = 0, hi = n;
    while (lo < hi) {
        int mid = (lo + hi) >> 1;
        if (a[mid] < key) lo = mid + 1; else hi = mid;
    }
    return lo;
}

__global__ void align_kernel(const int* __restrict__ uc1, int M1,
                             const int* __restrict__ keys0, int M0,
                             const int* __restrict__ keys2, int M2) {
    int i = blockIdx.x * blockDim.x + threadIdx.x;
    if (i >= M1) return;
    int b  = uc1[4 * i + 0];
    int cx = uc1[4 * i + 1];
    int cy = uc1[4 * i + 2];
    int cz = uc1[4 * i + 3];
    float rx = __fadd_rn(__fmul_rn(__fadd_rn((float)cx, 0.5f), 0.2f), -50.0f);
    float ry = __fadd_rn(__fmul_rn(__fadd_rn((float)cy, 0.5f), 0.2f), -50.0f);
    float rz = __fadd_rn(__fmul_rn(__fadd_rn((float)cz, 0.5f), 0.2f), -3.0f);
    float dx = __fsub_rn(rx, -50.0f);
    float dy = __fsub_rn(ry, -50.0f);
    float dz = __fsub_rn(rz, -3.0f);
    int match0;
    {
        int ix = (int)floorf(__fmul_rn(dx, 10.0f)); ix = min(max(ix, 0), 999);
        int iy = (int)floorf(__fmul_rn(dy, 10.0f)); iy = min(max(iy, 0), 999);
        int iz = (int)floorf(__fmul_rn(dz, 10.0f)); iz = min(max(iz, 0), 59);
        int k = b * 1000000000 + ix * 1000000 + iy * 1000 + iz;
        int lo = lower_bound_i32(keys0, M0, k);
        int idx = min(lo, M0 - 1); if (idx < 0) idx = 0;
        match0 = (keys0[idx] == k) ? idx : -1;
        g_idx0[i] = match0;
    }
    {
        int ix = (int)floorf(__fmul_rn(dx, 2.5f)); ix = min(max(ix, 0), 249);
        int iy = (int)floorf(__fmul_rn(dy, 2.5f)); iy = min(max(iy, 0), 249);
        int iz = (int)floorf(__fmul_rn(dz, 2.5f)); iz = min(max(iz, 0), 14);
        int k = b * 1000000000 + ix * 1000000 + iy * 1000 + iz;
        int lo = lower_bound_i32(keys2, M2, k);
        int idx = min(lo, M2 - 1); if (idx < 0) idx = 0;
        g_idx2[i] = (keys2[idx] == k) ? idx : -1;
    }
    // partition: matched-seg0 rows first
    if (match0 >= 0) {
        int p = atomicAdd(&g_cnt[0], 1);
        g_perm[p] = i;
    } else {
        int p = atomicAdd(&g_cnt[1], 1);
        g_perm[M1 - 1 - p] = i;
    }
}

// ---------------- host orchestration ----------------
extern "C" void kernel_launch(void* const* d_in, const int* in_sizes, int n_in,
                              void* d_out, int out_size) {
    (void)n_in; (void)out_size;
    const float* points = (const float*)d_in[0];
    const float* W1 = (const float*)d_in[1];
    const float* G1 = (const float*)d_in[2];
    const float* B1 = (const float*)d_in[3];
    const float* W2 = (const float*)d_in[4];
    const float* G2 = (const float*)d_in[5];
    const float* B2 = (const float*)d_in[6];
    const float* W3 = (const float*)d_in[7];
    const float* G3 = (const float*)d_in[8];
    const float* B3 = (const float*)d_in[9];
    const float* Wf = (const float*)d_in[10];
    const float* Gf = (const float*)d_in[11];
    const float* Bf = (const float*)d_in[12];
    const int* inv0 = (const int*)d_in[13];
    const int* inv1 = (const int*)d_in[14];
    const int* inv2 = (const int*)d_in[15];
    const int* keys0 = (const int*)d_in[16];
    const int* keys2 = (const int*)d_in[17];
    const int* uc1   = (const int*)d_in[18];

    int N  = in_sizes[0] / 4;
    int M0 = in_sizes[16];
    int M2 = in_sizes[17];
    int M1 = in_sizes[18] / 4;
    int maxM = M0 > M1 ? M0 : M1; if (M2 > maxM) maxM = M2;
    int3 Ms3 = make_int3(M0, M1, M2);

    float *t64, *t128, *feat, *y, *stats, *bnp;
    cudaGetSymbolAddress((void**)&t64,  g_t64);
    cudaGetSymbolAddress((void**)&t128, g_t128);
    cudaGetSymbolAddress((void**)&feat, g_feat);
    cudaGetSymbolAddress((void**)&y,    g_y);
    cudaGetSymbolAddress((void**)&stats, g_stats);
    cudaGetSymbolAddress((void**)&bnp,   g_bnp);

    zero_kernel<<<2048, 256>>>();
    wconv_kernel<<<(WTOT + 255) / 256, 256>>>(W2, W3, Wf);
    scatter_kernel<<<(N + 255) / 256, 256>>>(points, inv0, inv1, inv2, N);
    align_kernel<<<(M1 + 255) / 256, 256>>>(uc1, M1, keys0, M0, keys2, M2);

    // Layer 1 fused (mean + K=4 GEMM + stats)
    l1_kernel<<<dim3((maxM + 511) / 512, 3), 256>>>(W1, Ms3);
    finalize_kernel<<<dim3(1, 3), 64>>>(stats, bnp, G1, B1, 64, Ms3);
    xform_kernel<<<dim3(512, 3), 256>>>(t64, 64, Ms3, bnp);

    int gy = (maxM + 127) / 128;

    // Layer 2: [M,64] -> [M,128]
    mma_gemm<1><<<dim3(1, gy, 3), 256>>>(64, WOFF2, 128 * 64,
                                         t128, (size_t)MAXM * 128, Ms3, 128,
                                         stats + 4608);
    finalize_kernel<<<dim3(1, 3), 128>>>(stats + 4608, bnp + 4608, G2, B2, 128, Ms3);
    xform_kernel<<<dim3(512, 3), 256>>>(t128, 128, Ms3, bnp + 4608);

    // Layer 3: [M,128] -> [M,256]
    mma_gemm<1><<<dim3(2, gy, 3), 256>>>(128, WOFF3, 256 * 128,
                                         feat, (size_t)MAXM * 256, Ms3, 256,
                                         stats + 9216);
    finalize_kernel<<<dim3(1, 3), 256>>>(stats + 9216, bnp + 9216, G3, B3, 256, Ms3);
    xform_kernel<<<dim3(512, 3), 256>>>(feat, 256, Ms3, bnp + 9216);

    // Final: gather [M1,768] -> [M1,256], seg0-skip for unmatched rows
    mma_gemm<2><<<dim3(2, (M1 + 127) / 128, 1), 256>>>(768, WOFFF, 0,
                                                       y, 0, Ms3, 256,
                                                       stats + 13824);

    bnrelu_kernel<<<4096, 256>>>(y, (float*)d_out, M1, 256, stats + 13824, Gf, Bf);
}